// round 4
// baseline (speedup 1.0000x reference)
#include <cuda_runtime.h>
#include <cstdint>
#include <cstddef>

#define BB 4
#define TT 4096
#define DM 512
#define DH 64
#define BT (BB*TT)   // 16384

// ---------------- scratch (device globals; no allocation allowed) ----------
__device__ float g_q[BT*DH];     // tf32-rounded
__device__ float g_k[BT*DH];     // tf32-rounded
__device__ float g_v[BT*DH];     // tf32-rounded
__device__ float g_vsT[(size_t)BB*DH*TT];  // transposed v/colsum, tf32-rounded
__device__ float g_colsum[BT];

// ---------------- helpers ---------------------------------------------------
__device__ __forceinline__ float tf32r(float f) {
    uint32_t u;
    asm("cvt.rna.tf32.f32 %0, %1;" : "=r"(u) : "f"(f));
    return __uint_as_float(u);
}

// m16n8k8 tf32 mma, row.col, f32 accum
__device__ __forceinline__ void mma8(float4& c, const float4& a, const float2& bf) {
    uint32_t a0 = __float_as_uint(a.x), a1 = __float_as_uint(a.y);
    uint32_t a2 = __float_as_uint(a.z), a3 = __float_as_uint(a.w);
    uint32_t b0 = __float_as_uint(bf.x), b1 = __float_as_uint(bf.y);
    asm volatile(
        "mma.sync.aligned.m16n8k8.row.col.f32.tf32.tf32.f32 "
        "{%0,%1,%2,%3}, {%4,%5,%6,%7}, {%8,%9}, {%0,%1,%2,%3};"
        : "+f"(c.x), "+f"(c.y), "+f"(c.z), "+f"(c.w)
        : "r"(a0), "r"(a1), "r"(a2), "r"(a3), "r"(b0), "r"(b1));
}

__device__ __forceinline__ void cpcommit() {
    asm volatile("cp.async.commit_group;" ::: "memory");
}
template<int N> __device__ __forceinline__ void cpwait() {
    asm volatile("cp.async.wait_group %0;" :: "n"(N) : "memory");
}

// raw tiles: rows of 64 floats, smem row stride 68 floats (272 B) -> conflict-free frags
#define RSTRIDE 68
#define RAW128 (128*RSTRIDE)   // 8704 floats
#define RAW64  (64*RSTRIDE)    // 4352 floats

// copy nrows x 64 floats, global row stride gs (floats), into raw smem tile
__device__ __forceinline__ void stage_rows(float* sdst, const float* gsrc,
                                           int nrows, int gs) {
    uint32_t base = (uint32_t)__cvta_generic_to_shared(sdst);
    for (int c = threadIdx.x; c < nrows * 16; c += 256) {
        int r = c >> 4, ch = c & 15;
        asm volatile("cp.async.ca.shared.global [%0], [%1], 16;"
            :: "r"(base + r * (RSTRIDE*4) + ch * 16),
               "l"(gsrc + (size_t)r * gs + ch * 4) : "memory");
    }
}

// fragment loads from raw tiles (pre-rounded tf32 data)
__device__ __forceinline__ float4 ldA(const float* T, int r, int kk, int tc) {
    int o = r * RSTRIDE + kk * 8 + tc;
    return make_float4(T[o], T[o + 8*RSTRIDE], T[o + 4], T[o + 8*RSTRIDE + 4]);
}
__device__ __forceinline__ float2 ldB(const float* T, int n, int kk, int tc) {
    int o = n * RSTRIDE + kk * 8 + tc;
    return make_float2(T[o], T[o + 4]);
}

// ===========================================================================
// K1: QKV projections. out[r,h] = sum_d x[r,d]*W[h,d]; outputs tf32-rounded.
// grid (128, 3), 256 thr, double-buffered cp.async over 8 k-chunks of 64.
// ===========================================================================
__global__ __launch_bounds__(256, 2) void proj_kernel(
        const float* __restrict__ x,
        const float* __restrict__ Wq,
        const float* __restrict__ Wk,
        const float* __restrict__ Wv) {
    extern __shared__ float smem[];
    float* rX[2] = { smem, smem + RAW128 };
    float* rW[2] = { smem + 2*RAW128, smem + 2*RAW128 + RAW64 };

    const int row0 = blockIdx.x * 128;
    const float* W = (blockIdx.y == 0) ? Wq : (blockIdx.y == 1) ? Wk : Wv;
    float* out = (blockIdx.y == 0) ? g_q : (blockIdx.y == 1) ? g_k : g_v;

    const int tid = threadIdx.x, lane = tid & 31, w = tid >> 5;
    const int wm = w & 3, wn = w >> 2;
    const int g4 = lane >> 2, tc = lane & 3;

    float4 acc[2][4];
#pragma unroll
    for (int i = 0; i < 2; i++)
#pragma unroll
        for (int j = 0; j < 4; j++) acc[i][j] = make_float4(0.f,0.f,0.f,0.f);

    stage_rows(rX[0], x + (size_t)row0 * DM, 128, DM);
    stage_rows(rW[0], W, 64, DM);
    cpcommit();

    int bi = 0;
    for (int kc = 0; kc < 8; kc++, bi ^= 1) {
        if (kc + 1 < 8) {
            stage_rows(rX[bi^1], x + (size_t)row0 * DM + (kc+1)*64, 128, DM);
            stage_rows(rW[bi^1], W + (kc+1)*64, 64, DM);
            cpcommit();
            cpwait<1>();
        } else cpwait<0>();
        __syncthreads();

        const float* X = rX[bi]; const float* Wt = rW[bi];
#pragma unroll
        for (int kk = 0; kk < 8; kk++) {
            float4 a[2];
#pragma unroll
            for (int mt = 0; mt < 2; mt++) {
                float4 r = ldA(X, wm*32 + mt*16 + g4, kk, tc);
                a[mt] = make_float4(tf32r(r.x), tf32r(r.y), tf32r(r.z), tf32r(r.w));
            }
#pragma unroll
            for (int nt = 0; nt < 4; nt++) {
                float2 bv = ldB(Wt, wn*32 + nt*8 + g4, kk, tc);
                bv.x = tf32r(bv.x); bv.y = tf32r(bv.y);
                mma8(acc[0][nt], a[0], bv);
                mma8(acc[1][nt], a[1], bv);
            }
        }
        __syncthreads();
    }

#pragma unroll
    for (int mt = 0; mt < 2; mt++)
#pragma unroll
        for (int nt = 0; nt < 4; nt++) {
            int r = row0 + wm*32 + mt*16 + g4;
            int h = wn*32 + nt*8 + tc*2;
            float4 c = acc[mt][nt];
            *(float2*)&out[(size_t)r * DH + h] =
                make_float2(tf32r(c.x), tf32r(c.y));
            *(float2*)&out[(size_t)(r+8) * DH + h] =
                make_float2(tf32r(c.z), tf32r(c.w));
        }
}

// ===========================================================================
// zero kernels
// ===========================================================================
__global__ void zero_colsum_kernel() {
    int i = blockIdx.x * 256 + threadIdx.x;
    if (i < BT) g_colsum[i] = 0.f;
}
__global__ void zero_out_kernel(float* __restrict__ out) {
    int i = blockIdx.x * 256 + threadIdx.x;
    if (i < BT * DH) out[i] = 0.f;
}

// ===========================================================================
// K2: colsum[s] = sum_{t>=s} exp(q_t.k_s/8).
// grid (32 sb, BB, 4 strips), 256 thr. k staged once, q double-buffered.
// ===========================================================================
__global__ __launch_bounds__(256, 2) void colsum_kernel() {
    const int sb = blockIdx.x, b = blockIdx.y, strip = blockIdx.z;
    const int t_i0 = sb + strip;
    if (t_i0 >= 32) return;

    extern __shared__ float smem[];
    float* rK = smem;
    float* rQ[2] = { smem + RAW128, smem + 2*RAW128 };
    float* colbuf = smem + 3*RAW128;   // [128]

    const int tid = threadIdx.x, lane = tid & 31, w = tid >> 5;
    const int wm = w & 3, wn = w >> 2;
    const int g4 = lane >> 2, tc = lane & 3;
    const int s0 = sb * 128;

    if (tid < 128) colbuf[tid] = 0.f;

    stage_rows(rK, g_k + (size_t)(b*TT + s0) * DH, 128, DH);
    stage_rows(rQ[0], g_q + (size_t)(b*TT + t_i0*128) * DH, 128, DH);
    cpcommit();

    int bi = 0;
    for (int tidx = t_i0; tidx < 32; tidx += 4, bi ^= 1) {
        if (tidx + 4 < 32) {
            stage_rows(rQ[bi^1], g_q + (size_t)(b*TT + (tidx+4)*128) * DH, 128, DH);
            cpcommit();
            cpwait<1>();
        } else cpwait<0>();
        __syncthreads();

        const float* Q = rQ[bi];
        float4 acc[2][8];
#pragma unroll
        for (int i = 0; i < 2; i++)
#pragma unroll
            for (int j = 0; j < 8; j++) acc[i][j] = make_float4(0.f,0.f,0.f,0.f);

#pragma unroll
        for (int kk = 0; kk < 8; kk++) {
            float4 a0 = ldA(Q, wm*32 + g4, kk, tc);
            float4 a1 = ldA(Q, wm*32 + 16 + g4, kk, tc);
#pragma unroll
            for (int nt = 0; nt < 8; nt++) {
                float2 bv = ldB(rK, wn*64 + nt*8 + g4, kk, tc);
                mma8(acc[0][nt], a0, bv);
                mma8(acc[1][nt], a1, bv);
            }
        }

        const bool diag = (tidx == sb);
        const int t0 = tidx * 128;
        float colp[8][2];
#pragma unroll
        for (int nt = 0; nt < 8; nt++) { colp[nt][0] = 0.f; colp[nt][1] = 0.f; }

#pragma unroll
        for (int mt = 0; mt < 2; mt++) {
            int t = t0 + wm*32 + mt*16 + g4;
#pragma unroll
            for (int nt = 0; nt < 8; nt++) {
                float4 c = acc[mt][nt];
                float e0, e1, e2, e3;
                if (diag) {
                    int s = s0 + wn*64 + nt*8 + tc*2;
                    e0 = (s     <= t    ) ? __expf(c.x * 0.125f) : 0.f;
                    e1 = (s + 1 <= t    ) ? __expf(c.y * 0.125f) : 0.f;
                    e2 = (s     <= t + 8) ? __expf(c.z * 0.125f) : 0.f;
                    e3 = (s + 1 <= t + 8) ? __expf(c.w * 0.125f) : 0.f;
                } else {
                    e0 = __expf(c.x * 0.125f); e1 = __expf(c.y * 0.125f);
                    e2 = __expf(c.z * 0.125f); e3 = __expf(c.w * 0.125f);
                }
                colp[nt][0] += e0 + e2;
                colp[nt][1] += e1 + e3;
            }
        }

#pragma unroll
        for (int nt = 0; nt < 8; nt++)
#pragma unroll
            for (int par = 0; par < 2; par++) {
                float vsum = colp[nt][par];
                vsum += __shfl_xor_sync(0xffffffffu, vsum, 4);
                vsum += __shfl_xor_sync(0xffffffffu, vsum, 8);
                vsum += __shfl_xor_sync(0xffffffffu, vsum, 16);
                if (g4 == 0)
                    atomicAdd(&colbuf[wn*64 + nt*8 + tc*2 + par], vsum);
            }
        __syncthreads();
    }

    if (tid < 128)
        atomicAdd(&g_colsum[b*TT + s0 + tid], colbuf[tid]);
}

// ===========================================================================
// K3: vsT[b][h][s] = tf32r(v[s,h] / colsum[s])  — tiled transpose
// grid (TT/64, BB), 256 thr
// ===========================================================================
__global__ __launch_bounds__(256) void vscaleT_kernel() {
    __shared__ float tile[64][65];
    const int s0 = blockIdx.x * 64, b = blockIdx.y;
    for (int idx = threadIdx.x; idx < 4096; idx += 256) {
        int s = idx >> 6, h = idx & 63;
        tile[s][h] = tf32r(g_v[(size_t)(b*TT + s0 + s) * DH + h] /
                           g_colsum[b*TT + s0 + s]);
    }
    __syncthreads();
    for (int idx = threadIdx.x; idx < 4096; idx += 256) {
        int h = idx >> 6, s = idx & 63;
        g_vsT[((size_t)(b*DH + h)) * TT + s0 + s] = tile[s][h];
    }
}

// ===========================================================================
// K4: fused score-recompute + AV.  out[t,h] += sum_{s<=t} E[t,s]*vs[s,h]
// grid (32 tb reversed, 4 strips, BB), 256 thr. s-tiles of 64, k/v double-buf.
// ===========================================================================
__global__ __launch_bounds__(256, 2) void fused_av_kernel(float* __restrict__ out) {
    const int tb = 31 - blockIdx.x;
    const int strip = blockIdx.y;
    const int b = blockIdx.z;
    const int t0 = tb * 128;
    const int nstiles = 2*tb + 2;
    if (strip >= nstiles) return;

    extern __shared__ float smem[];
    float* rQ = smem;                                   // 128x64
    float* rK[2] = { smem + RAW128, smem + RAW128 + RAW64 };
    float* rV[2] = { smem + RAW128 + 2*RAW64, smem + RAW128 + 3*RAW64 };

    const int tid = threadIdx.x, lane = tid & 31, w = tid >> 5;
    const int g4 = lane >> 2, tc = lane & 3;
    const int srcA = (lane & ~3) | (tc >> 1);
    const int srcB = srcA + 2;
    const bool par = tc & 1;
    const float* vT = g_vsT + (size_t)b * DH * TT;

    stage_rows(rQ, g_q + (size_t)(b*TT + t0) * DH, 128, DH);
    stage_rows(rK[0], g_k + (size_t)(b*TT + strip*64) * DH, 64, DH);
    stage_rows(rV[0], vT + strip*64, 64, TT);
    cpcommit();

    float4 oacc[8];
#pragma unroll
    for (int n = 0; n < 8; n++) oacc[n] = make_float4(0.f,0.f,0.f,0.f);

    int bi = 0;
    for (int sidx = strip; sidx < nstiles; sidx += 4, bi ^= 1) {
        if (sidx + 4 < nstiles) {
            stage_rows(rK[bi^1], g_k + (size_t)(b*TT + (sidx+4)*64) * DH, 64, DH);
            stage_rows(rV[bi^1], vT + (sidx+4)*64, 64, TT);
            cpcommit();
            cpwait<1>();
        } else cpwait<0>();
        __syncthreads();

        const float* K = rK[bi]; const float* V = rV[bi];

        // score: warp rows t0 + w*16 .. +15, 64 s-cols
        float4 sacc[8];
#pragma unroll
        for (int j = 0; j < 8; j++) sacc[j] = make_float4(0.f,0.f,0.f,0.f);
#pragma unroll
        for (int kk = 0; kk < 8; kk++) {
            float4 a = ldA(rQ, w*16 + g4, kk, tc);
#pragma unroll
            for (int j = 0; j < 8; j++) {
                float2 bv = ldB(K, j*8 + g4, kk, tc);
                mma8(sacc[j], a, bv);
            }
        }

        const bool diag = (sidx >= 2*tb);
        const int trow = t0 + w*16 + g4;
        const int sbase = sidx * 64;

#pragma unroll
        for (int j = 0; j < 8; j++) {
            float4 c = sacc[j];
            float e0, e1, e2, e3;
            if (diag) {
                int s = sbase + j*8 + tc*2;
                e0 = (s     <= trow    ) ? __expf(c.x * 0.125f) : 0.f;
                e1 = (s + 1 <= trow    ) ? __expf(c.y * 0.125f) : 0.f;
                e2 = (s     <= trow + 8) ? __expf(c.z * 0.125f) : 0.f;
                e3 = (s + 1 <= trow + 8) ? __expf(c.w * 0.125f) : 0.f;
            } else {
                e0 = __expf(c.x * 0.125f); e1 = __expf(c.y * 0.125f);
                e2 = __expf(c.z * 0.125f); e3 = __expf(c.w * 0.125f);
            }
            // C-frag (cols tc*2, tc*2+1) -> A-frag (cols tc, tc+4)
            float s0a = __shfl_sync(0xffffffffu, e0, srcA);
            float s1a = __shfl_sync(0xffffffffu, e1, srcA);
            float s0b = __shfl_sync(0xffffffffu, e0, srcB);
            float s1b = __shfl_sync(0xffffffffu, e1, srcB);
            float s2a = __shfl_sync(0xffffffffu, e2, srcA);
            float s3a = __shfl_sync(0xffffffffu, e3, srcA);
            float s2b = __shfl_sync(0xffffffffu, e2, srcB);
            float s3b = __shfl_sync(0xffffffffu, e3, srcB);
            float4 af;
            af.x = tf32r(par ? s1a : s0a);
            af.y = tf32r(par ? s3a : s2a);
            af.z = tf32r(par ? s1b : s0b);
            af.w = tf32r(par ? s3b : s2b);
#pragma unroll
            for (int n = 0; n < 8; n++) {
                float2 bv = ldB(V, n*8 + g4, j, tc);
                mma8(oacc[n], af, bv);
            }
        }
        __syncthreads();
    }

    const size_t r = (size_t)(b*TT + t0 + w*16 + g4);
#pragma unroll
    for (int n = 0; n < 8; n++) {
        int h = n*8 + tc*2;
        atomicAdd(&out[r * DH + h],           oacc[n].x);
        atomicAdd(&out[r * DH + h + 1],       oacc[n].y);
        atomicAdd(&out[(r + 8) * DH + h],     oacc[n].z);
        atomicAdd(&out[(r + 8) * DH + h + 1], oacc[n].w);
    }
}

// ===========================================================================
// launch
// ===========================================================================
extern "C" void kernel_launch(void* const* d_in, const int* in_sizes, int n_in,
                              void* d_out, int out_size) {
    const float* x  = (const float*)d_in[0];
    const float* Wq = (const float*)d_in[1];
    const float* Wk = (const float*)d_in[2];
    const float* Wv = (const float*)d_in[3];
    float* out = (float*)d_out;

    const int smem_proj   = (2*RAW128 + 2*RAW64) * 4;        // 104448
    const int smem_colsum = (3*RAW128 + 128) * 4;            // 104960
    const int smem_fused  = (RAW128 + 4*RAW64) * 4;          // 104448

    cudaFuncSetAttribute(proj_kernel,     cudaFuncAttributeMaxDynamicSharedMemorySize, smem_proj);
    cudaFuncSetAttribute(colsum_kernel,   cudaFuncAttributeMaxDynamicSharedMemorySize, smem_colsum);
    cudaFuncSetAttribute(fused_av_kernel, cudaFuncAttributeMaxDynamicSharedMemorySize, smem_fused);

    proj_kernel<<<dim3(BT / 128, 3), 256, smem_proj>>>(x, Wq, Wk, Wv);
    zero_colsum_kernel<<<BT / 256, 256>>>();
    zero_out_kernel<<<(BT * DH) / 256, 256>>>(out);
    colsum_kernel<<<dim3(32, BB, 4), 256, smem_colsum>>>();
    vscaleT_kernel<<<dim3(TT / 64, BB), 256>>>();
    fused_av_kernel<<<dim3(32, 4, BB), 256, smem_fused>>>(out);
}

// round 7
// speedup vs baseline: 1.3617x; 1.3617x over previous
#include <cuda_runtime.h>
#include <cuda_fp16.h>
#include <cstdint>
#include <cstddef>

#define BB 4
#define TT 4096
#define DM 512
#define DH 64
#define BT (BB*TT)   // 16384

// ---------------- scratch (device globals; no allocation allowed) ----------
__device__ __half g_qh[BT*DH];
__device__ __half g_kh[BT*DH];
__device__ float  g_v[BT*DH];
__device__ float  g_vsP[BT*DH];    // vs pre-permuted into B-fragment order
__device__ float  g_colsum[BT];

// ---------------- helpers ---------------------------------------------------
__device__ __forceinline__ float tf32r(float f) {
    uint32_t u;
    asm("cvt.rna.tf32.f32 %0, %1;" : "=r"(u) : "f"(f));
    return __uint_as_float(u);
}

// tf32 m16n8k8 mma (AV + proj)
__device__ __forceinline__ void mma8(float4& c, const float4& a, const float2& bf) {
    uint32_t a0 = __float_as_uint(a.x), a1 = __float_as_uint(a.y);
    uint32_t a2 = __float_as_uint(a.z), a3 = __float_as_uint(a.w);
    uint32_t b0 = __float_as_uint(bf.x), b1 = __float_as_uint(bf.y);
    asm volatile(
        "mma.sync.aligned.m16n8k8.row.col.f32.tf32.tf32.f32 "
        "{%0,%1,%2,%3}, {%4,%5,%6,%7}, {%8,%9}, {%0,%1,%2,%3};"
        : "+f"(c.x), "+f"(c.y), "+f"(c.z), "+f"(c.w)
        : "r"(a0), "r"(a1), "r"(a2), "r"(a3), "r"(b0), "r"(b1));
}

// fp16 m16n8k16 mma, f32 accum (score GEMMs)
__device__ __forceinline__ void mmah(float4& c, const uint32_t* a,
                                     uint32_t b0, uint32_t b1) {
    asm volatile(
        "mma.sync.aligned.m16n8k16.row.col.f32.f16.f16.f32 "
        "{%0,%1,%2,%3}, {%4,%5,%6,%7}, {%8,%9}, {%0,%1,%2,%3};"
        : "+f"(c.x), "+f"(c.y), "+f"(c.z), "+f"(c.w)
        : "r"(a[0]), "r"(a[1]), "r"(a[2]), "r"(a[3]), "r"(b0), "r"(b1));
}

__device__ __forceinline__ void ldm4(uint32_t* f, uint32_t addr) {
    asm volatile("ldmatrix.sync.aligned.m8n8.x4.shared.b16 {%0,%1,%2,%3}, [%4];"
        : "=r"(f[0]), "=r"(f[1]), "=r"(f[2]), "=r"(f[3]) : "r"(addr));
}

__device__ __forceinline__ void cp16(uint32_t saddr, const void* g) {
    asm volatile("cp.async.ca.shared.global [%0], [%1], 16;"
        :: "r"(saddr), "l"(g) : "memory");
}
__device__ __forceinline__ void cpcommit() {
    asm volatile("cp.async.commit_group;" ::: "memory");
}
template<int N> __device__ __forceinline__ void cpwait() {
    asm volatile("cp.async.wait_group %0;" :: "n"(N) : "memory");
}

// fp16 tiles: 128 rows x 64 halfs, row stride 144 B (72 halfs)
#define HSB 144
#define HTILE (128*HSB)      // 18432 B

// stage 128x64 fp16 tile (row-major, 128B rows) via cp.async
__device__ __forceinline__ void stage_h(uint32_t sbase, const __half* g) {
    for (int c = threadIdx.x; c < 1024; c += 256) {
        int r = c >> 3, ch = c & 7;
        cp16(sbase + r * HSB + ch * 16, g + (size_t)r * DH + ch * 8);
    }
}

// ===========================================================================
// proj smem layouts (tf32, permuted fragment order — round-3 proven)
// ===========================================================================
#define F_KS (8*128 + 4)
#define G_KS8  (8*64 + 4)
#define F_SZ   (8*F_KS)
#define G_SZ8  (8*G_KS8)

#define FILL_F(Fp, LOAD4)                                                     \
    for (int c = threadIdx.x; c < 2048; c += 256) {                           \
        int row = c >> 4, q4 = c & 15;                                        \
        float4 v = LOAD4;                                                     \
        int kk = q4 >> 1, jh = q4 & 1;                                        \
        int rb = row >> 4, jl = (row >> 3) & 1, gr = row & 7;                 \
        int base = kk * F_KS + rb * 128 + gr * 16 + jh * 2 + jl;              \
        (Fp)[base +  0] = tf32r(v.x);                                         \
        (Fp)[base +  4] = tf32r(v.y);                                         \
        (Fp)[base +  8] = tf32r(v.z);                                         \
        (Fp)[base + 12] = tf32r(v.w);                                         \
    }

#define FILL_G_NMAJ(Gp, GKS, NCOLS, LOAD4)                                    \
    for (int c = threadIdx.x; c < (NCOLS)*16; c += 256) {                     \
        int n = c >> 4, q4 = c & 15;                                          \
        float4 v = LOAD4;                                                     \
        int kk = q4 >> 1, jh = q4 & 1;                                        \
        int nb = n >> 3, gc = n & 7;                                          \
        int base = kk * (GKS) + nb * 64 + gc * 8 + jh;                        \
        (Gp)[base + 0] = tf32r(v.x);                                          \
        (Gp)[base + 2] = tf32r(v.y);                                          \
        (Gp)[base + 4] = tf32r(v.z);                                          \
        (Gp)[base + 6] = tf32r(v.w);                                          \
    }

// ===========================================================================
// K1: QKV projections. q,k -> fp16; v -> fp32.
// ===========================================================================
__global__ __launch_bounds__(256) void proj_kernel(
        const float* __restrict__ x,
        const float* __restrict__ Wq,
        const float* __restrict__ Wk,
        const float* __restrict__ Wv) {
    extern __shared__ char smemc[];
    float* F = (float*)smemc;
    float* G = F + F_SZ;

    const int row0 = blockIdx.x * 128;
    const float* W = (blockIdx.y == 0) ? Wq : (blockIdx.y == 1) ? Wk : Wv;

    const int tid = threadIdx.x, lane = tid & 31, w = tid >> 5;
    const int wm = w & 3, wn = w >> 2;

    float4 acc[2][4];
#pragma unroll
    for (int i = 0; i < 2; i++)
#pragma unroll
        for (int j = 0; j < 4; j++) acc[i][j] = make_float4(0.f,0.f,0.f,0.f);

    for (int kc = 0; kc < DM; kc += 64) {
        FILL_F(F, (*(const float4*)&x[(size_t)(row0 + row) * DM + kc + q4 * 4]))
        FILL_G_NMAJ(G, G_KS8, 64, (*(const float4*)&W[(size_t)n * DM + kc + q4 * 4]))
        __syncthreads();
#pragma unroll
        for (int kk = 0; kk < 8; kk++) {
            float4 a0 = *(const float4*)&F[kk * F_KS + (wm * 2 + 0) * 128 + lane * 4];
            float4 a1 = *(const float4*)&F[kk * F_KS + (wm * 2 + 1) * 128 + lane * 4];
#pragma unroll
            for (int nt = 0; nt < 4; nt++) {
                float2 bv = *(const float2*)&G[kk * G_KS8 + (wn * 4 + nt) * 64 + lane * 2];
                mma8(acc[0][nt], a0, bv);
                mma8(acc[1][nt], a1, bv);
            }
        }
        __syncthreads();
    }

    const int gr = lane >> 2, tc = lane & 3;
#pragma unroll
    for (int mt = 0; mt < 2; mt++)
#pragma unroll
        for (int nt = 0; nt < 4; nt++) {
            int r = row0 + wm*32 + mt*16 + gr;
            int h = wn*32 + nt*8 + tc*2;
            float4 c = acc[mt][nt];
            if (blockIdx.y < 2) {
                __half* oh = (blockIdx.y == 0) ? g_qh : g_kh;
                *(__half2*)&oh[(size_t)r * DH + h]     = __floats2half2_rn(c.x, c.y);
                *(__half2*)&oh[(size_t)(r+8) * DH + h] = __floats2half2_rn(c.z, c.w);
            } else {
                *(float2*)&g_v[(size_t)r * DH + h]     = make_float2(c.x, c.y);
                *(float2*)&g_v[(size_t)(r+8) * DH + h] = make_float2(c.z, c.w);
            }
        }
}

// ===========================================================================
// zero kernels
// ===========================================================================
__global__ void zero_colsum_kernel() {
    int i = blockIdx.x * 256 + threadIdx.x;
    if (i < BT) g_colsum[i] = 0.f;
}
__global__ void zero_out_kernel(float* __restrict__ out) {
    int i = blockIdx.x * 256 + threadIdx.x;
    if (i < BT * DH) out[i] = 0.f;
}

// ===========================================================================
// K2: colsum[s] = sum_{t>=s} exp(q_t.k_s/8).  fp16 score MMA + ldmatrix.
// grid (32 sb, BB, 4 strips), 256 thr, 2 CTA/SM. k once, q double-buffered.
// ===========================================================================
__global__ __launch_bounds__(256, 2) void colsum_kernel() {
    const int sb = blockIdx.x, b = blockIdx.y, strip = blockIdx.z;
    const int t_i0 = sb + strip;
    if (t_i0 >= 32) return;

    extern __shared__ char smemc[];
    const uint32_t s32 = (uint32_t)__cvta_generic_to_shared(smemc);
    const uint32_t hk = s32;                // k tile
    const uint32_t hq[2] = { s32 + HTILE, s32 + 2*HTILE };
    float* colbuf = (float*)(smemc + 3*HTILE);   // [128]

    const int tid = threadIdx.x, lane = tid & 31, w = tid >> 5;
    const int wm = w & 3, wn = w >> 2;
    const int g4 = lane >> 2, tc = lane & 3;
    const int s0 = sb * 128;

    if (tid < 128) colbuf[tid] = 0.f;

    const uint32_t aoff = ((lane & 15) * 72 + ((lane >> 4) << 3)) * 2;
    const uint32_t boff = (((lane & 7) + (((lane >> 4) & 1) << 3)) * 72
                           + (((lane >> 3) & 1) << 3)) * 2;

    stage_h(hk, g_kh + (size_t)(b*TT + s0) * DH);
    stage_h(hq[0], g_qh + (size_t)(b*TT + t_i0*128) * DH);
    cpcommit();

    int bi = 0;
    for (int tidx = t_i0; tidx < 32; tidx += 4, bi ^= 1) {
        if (tidx + 4 < 32) {
            stage_h(hq[bi^1], g_qh + (size_t)(b*TT + (tidx+4)*128) * DH);
            cpcommit();
            cpwait<1>();
        } else cpwait<0>();
        __syncthreads();

        float4 acc[2][8];
#pragma unroll
        for (int i = 0; i < 2; i++)
#pragma unroll
            for (int j = 0; j < 8; j++) acc[i][j] = make_float4(0.f,0.f,0.f,0.f);

#pragma unroll
        for (int c4 = 0; c4 < 4; c4++) {
            const int kc = c4 * 16;
            uint32_t a0[4], a1[4];
            ldm4(a0, hq[bi] + (wm*32)      * HSB + kc*2 + aoff);
            ldm4(a1, hq[bi] + (wm*32 + 16) * HSB + kc*2 + aoff);
#pragma unroll
            for (int nt2 = 0; nt2 < 4; nt2++) {
                uint32_t bf[4];
                ldm4(bf, hk + (wn*64 + nt2*16) * HSB + kc*2 + boff);
                mmah(acc[0][nt2*2],   a0, bf[0], bf[1]);
                mmah(acc[0][nt2*2+1], a0, bf[2], bf[3]);
                mmah(acc[1][nt2*2],   a1, bf[0], bf[1]);
                mmah(acc[1][nt2*2+1], a1, bf[2], bf[3]);
            }
        }

        const bool diag = (tidx == sb);
        const int t0 = tidx * 128;
        float colp[8][2];
#pragma unroll
        for (int nt = 0; nt < 8; nt++) { colp[nt][0] = 0.f; colp[nt][1] = 0.f; }

#pragma unroll
        for (int mt = 0; mt < 2; mt++) {
            int t = t0 + wm*32 + mt*16 + g4;
#pragma unroll
            for (int nt = 0; nt < 8; nt++) {
                float4 c = acc[mt][nt];
                float e0, e1, e2, e3;
                if (diag) {
                    int s = s0 + wn*64 + nt*8 + tc*2;
                    e0 = (s     <= t    ) ? __expf(c.x * 0.125f) : 0.f;
                    e1 = (s + 1 <= t    ) ? __expf(c.y * 0.125f) : 0.f;
                    e2 = (s     <= t + 8) ? __expf(c.z * 0.125f) : 0.f;
                    e3 = (s + 1 <= t + 8) ? __expf(c.w * 0.125f) : 0.f;
                } else {
                    e0 = __expf(c.x * 0.125f); e1 = __expf(c.y * 0.125f);
                    e2 = __expf(c.z * 0.125f); e3 = __expf(c.w * 0.125f);
                }
                colp[nt][0] += e0 + e2;
                colp[nt][1] += e1 + e3;
            }
        }

#pragma unroll
        for (int nt = 0; nt < 8; nt++)
#pragma unroll
            for (int par = 0; par < 2; par++) {
                float vsum = colp[nt][par];
                vsum += __shfl_xor_sync(0xffffffffu, vsum, 4);
                vsum += __shfl_xor_sync(0xffffffffu, vsum, 8);
                vsum += __shfl_xor_sync(0xffffffffu, vsum, 16);
                if (g4 == 0)
                    atomicAdd(&colbuf[wn*64 + nt*8 + tc*2 + par], vsum);
            }
        __syncthreads();
    }

    if (tid < 128)
        atomicAdd(&g_colsum[b*TT + s0 + tid], colbuf[tid]);
}

// ===========================================================================
// K3: vsP = permute(tf32r(v/colsum)) into B-fragment order, per 128-s-tile.
// grid (32 stiles, BB), 256 thr
// ===========================================================================
__global__ __launch_bounds__(256) void vsP_kernel() {
    const int stile = blockIdx.x, b = blockIdx.y;
    float* dst = g_vsP + ((size_t)(b*32 + stile)) * 8192;
    for (int idx = threadIdx.x; idx < 8192; idx += 256) {
        int k = idx >> 6, h = idx & 63;
        int s = b*TT + stile*128 + k;
        float val = tf32r(g_v[(size_t)s * DH + h] / g_colsum[s]);
        int P = (k >> 3) * 512 + (h >> 3) * 64 + ((h >> 2) & 1) * 32
              + (h & 3) * 8 + ((k >> 2) & 1) + (k & 3) * 2;
        dst[P] = val;
    }
}

// ===========================================================================
// K4: fused score-recompute (fp16) + AV (tf32).
// grid (32 tb reversed, 4 strips, BB), 256 thr, 2 CTA/SM. s-tiles of 128.
// ===========================================================================
__global__ __launch_bounds__(256, 2) void fused_av_kernel(float* __restrict__ out) {
    const int tb = 31 - blockIdx.x;
    const int strip = blockIdx.y;
    const int b = blockIdx.z;
    const int t0 = tb * 128;
    if (strip > tb) return;

    extern __shared__ char smemc[];
    const uint32_t s32 = (uint32_t)__cvta_generic_to_shared(smemc);
    const uint32_t hq = s32;
    const uint32_t hk[2] = { s32 + HTILE, s32 + 2*HTILE };
    const uint32_t gv32 = s32 + 3*HTILE;
    float* Gv = (float*)(smemc + 3*HTILE);     // 8192 floats

    const int tid = threadIdx.x, lane = tid & 31, w = tid >> 5;
    const int g4 = lane >> 2, tc = lane & 3;
    const int srcA = (lane & ~3) | (tc >> 1);
    const int srcB = srcA + 2;
    const bool par = tc & 1;

    const uint32_t aoff = ((lane & 15) * 72 + ((lane >> 4) << 3)) * 2;
    const uint32_t boff = (((lane & 7) + (((lane >> 4) & 1) << 3)) * 72
                           + (((lane >> 3) & 1) << 3)) * 2;

    stage_h(hq, g_qh + (size_t)(b*TT + t0) * DH);
    stage_h(hk[0], g_kh + (size_t)(b*TT + strip*128) * DH);
    cpcommit();

    float4 oacc[8];
#pragma unroll
    for (int n = 0; n < 8; n++) oacc[n] = make_float4(0.f,0.f,0.f,0.f);

    int bi = 0;
    for (int sidx = strip; sidx <= tb; sidx += 4, bi ^= 1) {
        // Gv for this tile (own group)
        {
            const float* src = g_vsP + ((size_t)(b*32 + sidx)) * 8192;
            for (int c = tid; c < 2048; c += 256)
                cp16(gv32 + c*16, src + c*4);
            cpcommit();
        }
        if (sidx + 4 <= tb) {
            stage_h(hk[bi^1], g_kh + (size_t)(b*TT + (sidx+4)*128) * DH);
            cpcommit();
            cpwait<1>();
        } else cpwait<0>();
        __syncthreads();

        const bool diag = (sidx == tb);
        const int trow = t0 + w*16 + g4;
        const int sbase = sidx * 128;

#pragma unroll
        for (int half = 0; half < 2; half++) {
            float4 sacc[8];
#pragma unroll
            for (int j = 0; j < 8; j++) sacc[j] = make_float4(0.f,0.f,0.f,0.f);
#pragma unroll
            for (int c4 = 0; c4 < 4; c4++) {
                const int kc = c4 * 16;
                uint32_t a[4];
                ldm4(a, hq + (w*16) * HSB + kc*2 + aoff);
#pragma unroll
                for (int nt2 = 0; nt2 < 4; nt2++) {
                    uint32_t bf[4];
                    ldm4(bf, hk[bi] + (half*64 + nt2*16) * HSB + kc*2 + boff);
                    mmah(sacc[nt2*2],   a, bf[0], bf[1]);
                    mmah(sacc[nt2*2+1], a, bf[2], bf[3]);
                }
            }

#pragma unroll
            for (int j = 0; j < 8; j++) {
                const int gj = half*8 + j;
                float4 c = sacc[j];
                float e0, e1, e2, e3;
                if (diag) {
                    int s = sbase + gj*8 + tc*2;
                    e0 = (s     <= trow    ) ? __expf(c.x * 0.125f) : 0.f;
                    e1 = (s + 1 <= trow    ) ? __expf(c.y * 0.125f) : 0.f;
                    e2 = (s     <= trow + 8) ? __expf(c.z * 0.125f) : 0.f;
                    e3 = (s + 1 <= trow + 8) ? __expf(c.w * 0.125f) : 0.f;
                } else {
                    e0 = __expf(c.x * 0.125f); e1 = __expf(c.y * 0.125f);
                    e2 = __expf(c.z * 0.125f); e3 = __expf(c.w * 0.125f);
                }
                // C-frag (cols tc*2, tc*2+1) -> A-frag (cols tc, tc+4)
                float s0a = __shfl_sync(0xffffffffu, e0, srcA);
                float s1a = __shfl_sync(0xffffffffu, e1, srcA);
                float s0b = __shfl_sync(0xffffffffu, e0, srcB);
                float s1b = __shfl_sync(0xffffffffu, e1, srcB);
                float s2a = __shfl_sync(0xffffffffu, e2, srcA);
                float s3a = __shfl_sync(0xffffffffu, e3, srcA);
                float s2b = __shfl_sync(0xffffffffu, e2, srcB);
                float s3b = __shfl_sync(0xffffffffu, e3, srcB);
                float4 af;
                af.x = tf32r(par ? s1a : s0a);
                af.y = tf32r(par ? s3a : s2a);
                af.z = tf32r(par ? s1b : s0b);
                af.w = tf32r(par ? s3b : s2b);
#pragma unroll
                for (int n = 0; n < 8; n++) {
                    float2 bv = *(const float2*)&Gv[gj*512 + n*64 + lane*2];
                    mma8(oacc[n], af, bv);
                }
            }
        }
        __syncthreads();
    }

    const size_t r = (size_t)(b*TT + t0 + w*16 + g4);
#pragma unroll
    for (int n = 0; n < 8; n++) {
        int h = n*8 + tc*2;
        atomicAdd(&out[r * DH + h],           oacc[n].x);
        atomicAdd(&out[r * DH + h + 1],       oacc[n].y);
        atomicAdd(&out[(r + 8) * DH + h],     oacc[n].z);
        atomicAdd(&out[(r + 8) * DH + h + 1], oacc[n].w);
    }
}

// ===========================================================================
// launch
// ===========================================================================
extern "C" void kernel_launch(void* const* d_in, const int* in_sizes, int n_in,
                              void* d_out, int out_size) {
    const float* x  = (const float*)d_in[0];
    const float* Wq = (const float*)d_in[1];
    const float* Wk = (const float*)d_in[2];
    const float* Wv = (const float*)d_in[3];
    float* out = (float*)d_out;

    const int smem_proj   = (F_SZ + G_SZ8) * 4;       // 49408
    const int smem_colsum = 3*HTILE + 512;            // 55808
    const int smem_fused  = 3*HTILE + 32768;          // 88064

    cudaFuncSetAttribute(proj_kernel,     cudaFuncAttributeMaxDynamicSharedMemorySize, smem_proj);
    cudaFuncSetAttribute(colsum_kernel,   cudaFuncAttributeMaxDynamicSharedMemorySize, smem_colsum);
    cudaFuncSetAttribute(fused_av_kernel, cudaFuncAttributeMaxDynamicSharedMemorySize, smem_fused);

    proj_kernel<<<dim3(BT / 128, 3), 256, smem_proj>>>(x, Wq, Wk, Wv);
    zero_colsum_kernel<<<BT / 256, 256>>>();
    zero_out_kernel<<<(BT * DH) / 256, 256>>>(out);
    colsum_kernel<<<dim3(32, BB, 4), 256, smem_colsum>>>();
    vsP_kernel<<<dim3(32, BB), 256>>>();
    fused_av_kernel<<<dim3(32, 4, BB), 256, smem_fused>>>(out);
}

// round 8
// speedup vs baseline: 1.4909x; 1.0949x over previous
#include <cuda_runtime.h>
#include <cuda_fp16.h>
#include <cstdint>
#include <cstddef>

#define BB 4
#define TT 4096
#define DM 512
#define DH 64
#define BT (BB*TT)   // 16384

// ---------------- scratch (device globals; no allocation allowed) ----------
__device__ __half g_qh[BT*DH];
__device__ __half g_kh[BT*DH];
__device__ float  g_v[BT*DH];
__device__ __half g_vshT[(size_t)BB*DH*TT];   // transposed scaled v, fp16
__device__ float  g_colsum[BT];
__device__ __half g_E[(size_t)BB*TT*TT];      // masked exp scores, fp16

// ---------------- helpers ---------------------------------------------------
__device__ __forceinline__ float tf32r(float f) {
    uint32_t u;
    asm("cvt.rna.tf32.f32 %0, %1;" : "=r"(u) : "f"(f));
    return __uint_as_float(u);
}

// tf32 m16n8k8 mma (proj only)
__device__ __forceinline__ void mma8(float4& c, const float4& a, const float2& bf) {
    uint32_t a0 = __float_as_uint(a.x), a1 = __float_as_uint(a.y);
    uint32_t a2 = __float_as_uint(a.z), a3 = __float_as_uint(a.w);
    uint32_t b0 = __float_as_uint(bf.x), b1 = __float_as_uint(bf.y);
    asm volatile(
        "mma.sync.aligned.m16n8k8.row.col.f32.tf32.tf32.f32 "
        "{%0,%1,%2,%3}, {%4,%5,%6,%7}, {%8,%9}, {%0,%1,%2,%3};"
        : "+f"(c.x), "+f"(c.y), "+f"(c.z), "+f"(c.w)
        : "r"(a0), "r"(a1), "r"(a2), "r"(a3), "r"(b0), "r"(b1));
}

// fp16 m16n8k16 mma, f32 accum
__device__ __forceinline__ void mmah(float4& c, const uint32_t* a,
                                     uint32_t b0, uint32_t b1) {
    asm volatile(
        "mma.sync.aligned.m16n8k16.row.col.f32.f16.f16.f32 "
        "{%0,%1,%2,%3}, {%4,%5,%6,%7}, {%8,%9}, {%0,%1,%2,%3};"
        : "+f"(c.x), "+f"(c.y), "+f"(c.z), "+f"(c.w)
        : "r"(a[0]), "r"(a[1]), "r"(a[2]), "r"(a[3]), "r"(b0), "r"(b1));
}

__device__ __forceinline__ void ldm4(uint32_t* f, uint32_t addr) {
    asm volatile("ldmatrix.sync.aligned.m8n8.x4.shared.b16 {%0,%1,%2,%3}, [%4];"
        : "=r"(f[0]), "=r"(f[1]), "=r"(f[2]), "=r"(f[3]) : "r"(addr));
}

__device__ __forceinline__ void cp16(uint32_t saddr, const void* g) {
    asm volatile("cp.async.ca.shared.global [%0], [%1], 16;"
        :: "r"(saddr), "l"(g) : "memory");
}
__device__ __forceinline__ void cpcommit() {
    asm volatile("cp.async.commit_group;" ::: "memory");
}
template<int N> __device__ __forceinline__ void cpwait() {
    asm volatile("cp.async.wait_group %0;" :: "n"(N) : "memory");
}

// fp16 q/k tiles: 128 rows x 64 halfs, stride 144 B
#define HSB 144
#define HTILE (128*HSB)      // 18432 B
// E tiles: 128 rows x 128 halfs, stride 272 B.  V tiles: 64 rows x 128, stride 272.
#define ESB 272
#define ETILE (128*ESB)      // 34816 B
#define VTILE (64*ESB)       // 17408 B

__device__ __forceinline__ void stage_h(uint32_t sbase, const __half* g) {
    for (int c = threadIdx.x; c < 1024; c += 256) {
        int r = c >> 3, ch = c & 7;
        cp16(sbase + r * HSB + ch * 16, g + (size_t)r * DH + ch * 8);
    }
}
// stage 128x128 fp16 E tile; global row stride TT halfs
__device__ __forceinline__ void stage_E(uint32_t sbase, const __half* g) {
    for (int c = threadIdx.x; c < 2048; c += 256) {
        int r = c >> 4, ch = c & 15;
        cp16(sbase + r * ESB + ch * 16, g + (size_t)r * TT + ch * 8);
    }
}
// stage 64x128 fp16 V tile; global row stride TT halfs
__device__ __forceinline__ void stage_V(uint32_t sbase, const __half* g) {
    for (int c = threadIdx.x; c < 1024; c += 256) {
        int r = c >> 4, ch = c & 15;
        cp16(sbase + r * ESB + ch * 16, g + (size_t)r * TT + ch * 8);
    }
}

// ===========================================================================
// proj smem layouts (tf32 fragment order — proven)
// ===========================================================================
#define F_KS (8*128 + 4)
#define G_KS8  (8*64 + 4)
#define F_SZ   (8*F_KS)
#define G_SZ8  (8*G_KS8)

#define FILL_F(Fp, LOAD4)                                                     \
    for (int c = threadIdx.x; c < 2048; c += 256) {                           \
        int row = c >> 4, q4 = c & 15;                                        \
        float4 v = LOAD4;                                                     \
        int kk = q4 >> 1, jh = q4 & 1;                                        \
        int rb = row >> 4, jl = (row >> 3) & 1, gr = row & 7;                 \
        int base = kk * F_KS + rb * 128 + gr * 16 + jh * 2 + jl;              \
        (Fp)[base +  0] = tf32r(v.x);                                         \
        (Fp)[base +  4] = tf32r(v.y);                                         \
        (Fp)[base +  8] = tf32r(v.z);                                         \
        (Fp)[base + 12] = tf32r(v.w);                                         \
    }

#define FILL_G_NMAJ(Gp, GKS, NCOLS, LOAD4)                                    \
    for (int c = threadIdx.x; c < (NCOLS)*16; c += 256) {                     \
        int n = c >> 4, q4 = c & 15;                                          \
        float4 v = LOAD4;                                                     \
        int kk = q4 >> 1, jh = q4 & 1;                                        \
        int nb = n >> 3, gc = n & 7;                                          \
        int base = kk * (GKS) + nb * 64 + gc * 8 + jh;                        \
        (Gp)[base + 0] = tf32r(v.x);                                          \
        (Gp)[base + 2] = tf32r(v.y);                                          \
        (Gp)[base + 4] = tf32r(v.z);                                          \
        (Gp)[base + 6] = tf32r(v.w);                                          \
    }

// ===========================================================================
// K1: QKV projections. q,k -> fp16; v -> fp32.
// ===========================================================================
__global__ __launch_bounds__(256) void proj_kernel(
        const float* __restrict__ x,
        const float* __restrict__ Wq,
        const float* __restrict__ Wk,
        const float* __restrict__ Wv) {
    extern __shared__ char smemc[];
    float* F = (float*)smemc;
    float* G = F + F_SZ;

    const int row0 = blockIdx.x * 128;
    const float* W = (blockIdx.y == 0) ? Wq : (blockIdx.y == 1) ? Wk : Wv;

    const int tid = threadIdx.x, lane = tid & 31, w = tid >> 5;
    const int wm = w & 3, wn = w >> 2;

    float4 acc[2][4];
#pragma unroll
    for (int i = 0; i < 2; i++)
#pragma unroll
        for (int j = 0; j < 4; j++) acc[i][j] = make_float4(0.f,0.f,0.f,0.f);

    for (int kc = 0; kc < DM; kc += 64) {
        FILL_F(F, (*(const float4*)&x[(size_t)(row0 + row) * DM + kc + q4 * 4]))
        FILL_G_NMAJ(G, G_KS8, 64, (*(const float4*)&W[(size_t)n * DM + kc + q4 * 4]))
        __syncthreads();
#pragma unroll
        for (int kk = 0; kk < 8; kk++) {
            float4 a0 = *(const float4*)&F[kk * F_KS + (wm * 2 + 0) * 128 + lane * 4];
            float4 a1 = *(const float4*)&F[kk * F_KS + (wm * 2 + 1) * 128 + lane * 4];
#pragma unroll
            for (int nt = 0; nt < 4; nt++) {
                float2 bv = *(const float2*)&G[kk * G_KS8 + (wn * 4 + nt) * 64 + lane * 2];
                mma8(acc[0][nt], a0, bv);
                mma8(acc[1][nt], a1, bv);
            }
        }
        __syncthreads();
    }

    const int gr = lane >> 2, tc = lane & 3;
#pragma unroll
    for (int mt = 0; mt < 2; mt++)
#pragma unroll
        for (int nt = 0; nt < 4; nt++) {
            int r = row0 + wm*32 + mt*16 + gr;
            int h = wn*32 + nt*8 + tc*2;
            float4 c = acc[mt][nt];
            if (blockIdx.y < 2) {
                __half* oh = (blockIdx.y == 0) ? g_qh : g_kh;
                *(__half2*)&oh[(size_t)r * DH + h]     = __floats2half2_rn(c.x, c.y);
                *(__half2*)&oh[(size_t)(r+8) * DH + h] = __floats2half2_rn(c.z, c.w);
            } else {
                *(float2*)&g_v[(size_t)r * DH + h]     = make_float2(c.x, c.y);
                *(float2*)&g_v[(size_t)(r+8) * DH + h] = make_float2(c.z, c.w);
            }
        }
}

// ===========================================================================
// zero kernels
// ===========================================================================
__global__ void zero_colsum_kernel() {
    int i = blockIdx.x * 256 + threadIdx.x;
    if (i < BT) g_colsum[i] = 0.f;
}
__global__ void zero_out_kernel(float* __restrict__ out) {
    int i = blockIdx.x * 256 + threadIdx.x;
    if (i < BT * DH) out[i] = 0.f;
}

// ===========================================================================
// K2: colsum + E materialization.
// colsum[s] = sum_{t>=s} exp(q_t.k_s/8);  g_E[b][t][s] = masked exp (fp16).
// grid (32 sb, BB, 4 strips), 256 thr, 2 CTA/SM.
// ===========================================================================
__global__ __launch_bounds__(256, 2) void colsum_kernel() {
    const int sb = blockIdx.x, b = blockIdx.y, strip = blockIdx.z;
    const int t_i0 = sb + strip;
    if (t_i0 >= 32) return;

    extern __shared__ char smemc[];
    const uint32_t s32 = (uint32_t)__cvta_generic_to_shared(smemc);
    const uint32_t hk = s32;
    const uint32_t hq[2] = { s32 + HTILE, s32 + 2*HTILE };
    float* colbuf = (float*)(smemc + 3*HTILE);   // [128]

    const int tid = threadIdx.x, lane = tid & 31, w = tid >> 5;
    const int wm = w & 3, wn = w >> 2;
    const int g4 = lane >> 2, tc = lane & 3;
    const int s0 = sb * 128;

    if (tid < 128) colbuf[tid] = 0.f;

    const uint32_t aoff = ((lane & 15) * 72 + ((lane >> 4) << 3)) * 2;
    const uint32_t boff = (((lane & 7) + (((lane >> 4) & 1) << 3)) * 72
                           + (((lane >> 3) & 1) << 3)) * 2;

    stage_h(hk, g_kh + (size_t)(b*TT + s0) * DH);
    stage_h(hq[0], g_qh + (size_t)(b*TT + t_i0*128) * DH);
    cpcommit();

    int bi = 0;
    for (int tidx = t_i0; tidx < 32; tidx += 4, bi ^= 1) {
        if (tidx + 4 < 32) {
            stage_h(hq[bi^1], g_qh + (size_t)(b*TT + (tidx+4)*128) * DH);
            cpcommit();
            cpwait<1>();
        } else cpwait<0>();
        __syncthreads();

        float4 acc[2][8];
#pragma unroll
        for (int i = 0; i < 2; i++)
#pragma unroll
            for (int j = 0; j < 8; j++) acc[i][j] = make_float4(0.f,0.f,0.f,0.f);

#pragma unroll
        for (int c4 = 0; c4 < 4; c4++) {
            const int kc = c4 * 16;
            uint32_t a0[4], a1[4];
            ldm4(a0, hq[bi] + (wm*32)      * HSB + kc*2 + aoff);
            ldm4(a1, hq[bi] + (wm*32 + 16) * HSB + kc*2 + aoff);
#pragma unroll
            for (int nt2 = 0; nt2 < 4; nt2++) {
                uint32_t bf[4];
                ldm4(bf, hk + (wn*64 + nt2*16) * HSB + kc*2 + boff);
                mmah(acc[0][nt2*2],   a0, bf[0], bf[1]);
                mmah(acc[0][nt2*2+1], a0, bf[2], bf[3]);
                mmah(acc[1][nt2*2],   a1, bf[0], bf[1]);
                mmah(acc[1][nt2*2+1], a1, bf[2], bf[3]);
            }
        }

        const bool diag = (tidx == sb);
        const int t0 = tidx * 128;
        float colp[8][2];
#pragma unroll
        for (int nt = 0; nt < 8; nt++) { colp[nt][0] = 0.f; colp[nt][1] = 0.f; }

#pragma unroll
        for (int mt = 0; mt < 2; mt++) {
            int t = t0 + wm*32 + mt*16 + g4;
#pragma unroll
            for (int nt = 0; nt < 8; nt++) {
                float4 c = acc[mt][nt];
                int s = s0 + wn*64 + nt*8 + tc*2;
                float e0, e1, e2, e3;
                if (diag) {
                    e0 = (s     <= t    ) ? __expf(c.x * 0.125f) : 0.f;
                    e1 = (s + 1 <= t    ) ? __expf(c.y * 0.125f) : 0.f;
                    e2 = (s     <= t + 8) ? __expf(c.z * 0.125f) : 0.f;
                    e3 = (s + 1 <= t + 8) ? __expf(c.w * 0.125f) : 0.f;
                } else {
                    e0 = __expf(c.x * 0.125f); e1 = __expf(c.y * 0.125f);
                    e2 = __expf(c.z * 0.125f); e3 = __expf(c.w * 0.125f);
                }
                *(__half2*)&g_E[((size_t)(b*TT + t))*TT + s]     = __floats2half2_rn(e0, e1);
                *(__half2*)&g_E[((size_t)(b*TT + t + 8))*TT + s] = __floats2half2_rn(e2, e3);
                colp[nt][0] += e0 + e2;
                colp[nt][1] += e1 + e3;
            }
        }

#pragma unroll
        for (int nt = 0; nt < 8; nt++)
#pragma unroll
            for (int par = 0; par < 2; par++) {
                float vsum = colp[nt][par];
                vsum += __shfl_xor_sync(0xffffffffu, vsum, 4);
                vsum += __shfl_xor_sync(0xffffffffu, vsum, 8);
                vsum += __shfl_xor_sync(0xffffffffu, vsum, 16);
                if (g4 == 0)
                    atomicAdd(&colbuf[wn*64 + nt*8 + tc*2 + par], vsum);
            }
        __syncthreads();
    }

    if (tid < 128)
        atomicAdd(&g_colsum[b*TT + s0 + tid], colbuf[tid]);
}

// ===========================================================================
// K3: g_vshT[b][h][s] = fp16(v[s,h] / colsum[s])  — tiled transpose
// grid (TT/64, BB), 256 thr
// ===========================================================================
__global__ __launch_bounds__(256) void vshT_kernel() {
    __shared__ float tile[64][65];
    const int s0 = blockIdx.x * 64, b = blockIdx.y;
    for (int idx = threadIdx.x; idx < 4096; idx += 256) {
        int s = idx >> 6, h = idx & 63;
        tile[s][h] = g_v[(size_t)(b*TT + s0 + s) * DH + h] / g_colsum[b*TT + s0 + s];
    }
    __syncthreads();
    for (int idx = threadIdx.x; idx < 2048; idx += 256) {
        int h = idx >> 5, sp = idx & 31;
        *(__half2*)&g_vshT[((size_t)(b*DH + h)) * TT + s0 + sp*2] =
            __floats2half2_rn(tile[sp*2][h], tile[sp*2+1][h]);
    }
}

// ===========================================================================
// K4: pure fp16 GEMM AV.  out[t,h] += sum_s E[t,s] * vs[s,h]
// grid (32 tb reversed, 4 strips, BB), 256 thr, 2 CTA/SM. s-tiles of 128,
// E and V double-buffered via cp.async. Warp = 16 t-rows x 64 h.
// ===========================================================================
__global__ __launch_bounds__(256, 2) void av_kernel(float* __restrict__ out) {
    const int tb = 31 - blockIdx.x;
    const int strip = blockIdx.y;
    const int b = blockIdx.z;
    const int t0 = tb * 128;
    if (strip > tb) return;

    extern __shared__ char smemc[];
    const uint32_t s32 = (uint32_t)__cvta_generic_to_shared(smemc);
    const uint32_t eb[2] = { s32, s32 + ETILE };
    const uint32_t vb[2] = { s32 + 2*ETILE, s32 + 2*ETILE + VTILE };

    const int tid = threadIdx.x, lane = tid & 31, w = tid >> 5;
    const int g4 = lane >> 2, tc = lane & 3;

    const uint32_t aoff = (lane & 15) * ESB + ((lane >> 4) << 4);
    const uint32_t boff = ((lane & 7) + (((lane >> 4) & 1) << 3)) * ESB
                        + (((lane >> 3) & 1) << 4);

    const __half* Ebase = g_E + ((size_t)(b*TT + t0)) * TT;
    const __half* Vbase = g_vshT + (size_t)b * DH * TT;

    stage_E(eb[0], Ebase + strip*128);
    stage_V(vb[0], Vbase + strip*128);
    cpcommit();

    float4 oacc[8];
#pragma unroll
    for (int n = 0; n < 8; n++) oacc[n] = make_float4(0.f,0.f,0.f,0.f);

    int bi = 0;
    for (int sidx = strip; sidx <= tb; sidx += 4, bi ^= 1) {
        if (sidx + 4 <= tb) {
            stage_E(eb[bi^1], Ebase + (sidx+4)*128);
            stage_V(vb[bi^1], Vbase + (sidx+4)*128);
            cpcommit();
            cpwait<1>();
        } else cpwait<0>();
        __syncthreads();

#pragma unroll
        for (int c8 = 0; c8 < 8; c8++) {
            const int kc = c8 * 16;
            uint32_t a[4];
            ldm4(a, eb[bi] + (w*16) * ESB + kc*2 + aoff);
#pragma unroll
            for (int nt2 = 0; nt2 < 4; nt2++) {
                uint32_t bf[4];
                ldm4(bf, vb[bi] + (nt2*16) * ESB + kc*2 + boff);
                mmah(oacc[nt2*2],   a, bf[0], bf[1]);
                mmah(oacc[nt2*2+1], a, bf[2], bf[3]);
            }
        }
        __syncthreads();
    }

    const size_t r = (size_t)(b*TT + t0 + w*16 + g4);
#pragma unroll
    for (int n = 0; n < 8; n++) {
        int h = n*8 + tc*2;
        atomicAdd(&out[r * DH + h],           oacc[n].x);
        atomicAdd(&out[r * DH + h + 1],       oacc[n].y);
        atomicAdd(&out[(r + 8) * DH + h],     oacc[n].z);
        atomicAdd(&out[(r + 8) * DH + h + 1], oacc[n].w);
    }
}

// ===========================================================================
// launch
// ===========================================================================
extern "C" void kernel_launch(void* const* d_in, const int* in_sizes, int n_in,
                              void* d_out, int out_size) {
    const float* x  = (const float*)d_in[0];
    const float* Wq = (const float*)d_in[1];
    const float* Wk = (const float*)d_in[2];
    const float* Wv = (const float*)d_in[3];
    float* out = (float*)d_out;

    const int smem_proj   = (F_SZ + G_SZ8) * 4;       // 49408
    const int smem_colsum = 3*HTILE + 512;            // 55808
    const int smem_av     = 2*ETILE + 2*VTILE;        // 104448

    cudaFuncSetAttribute(proj_kernel,   cudaFuncAttributeMaxDynamicSharedMemorySize, smem_proj);
    cudaFuncSetAttribute(colsum_kernel, cudaFuncAttributeMaxDynamicSharedMemorySize, smem_colsum);
    cudaFuncSetAttribute(av_kernel,     cudaFuncAttributeMaxDynamicSharedMemorySize, smem_av);

    proj_kernel<<<dim3(BT / 128, 3), 256, smem_proj>>>(x, Wq, Wk, Wv);
    zero_colsum_kernel<<<BT / 256, 256>>>();
    zero_out_kernel<<<(BT * DH) / 256, 256>>>(out);
    colsum_kernel<<<dim3(32, BB, 4), 256, smem_colsum>>>();
    vshT_kernel<<<dim3(TT / 64, BB), 256>>>();
    av_kernel<<<dim3(32, 4, BB), 256, smem_av>>>(out);
}

// round 9
// speedup vs baseline: 1.5493x; 1.0392x over previous
#include <cuda_runtime.h>
#include <cuda_fp16.h>
#include <cstdint>
#include <cstddef>

#define BB 4
#define TT 4096
#define DM 512
#define DH 64
#define BT (BB*TT)   // 16384

// ---------------- scratch (device globals; no allocation allowed) ----------
__device__ __half g_qh[BT*DH];
__device__ __half g_kh[BT*DH];
__device__ float  g_v[BT*DH];
__device__ __half g_vshT[(size_t)BB*DH*TT];   // transposed scaled v, fp16
__device__ float  g_colsum[BT];
__device__ __half g_E[(size_t)BB*TT*TT];      // masked exp scores, fp16

// ---------------- helpers ---------------------------------------------------
__device__ __forceinline__ float tf32r(float f) {
    uint32_t u;
    asm("cvt.rna.tf32.f32 %0, %1;" : "=r"(u) : "f"(f));
    return __uint_as_float(u);
}

// tf32 m16n8k8 mma (proj only)
__device__ __forceinline__ void mma8(float4& c, const float4& a, const float2& bf) {
    uint32_t a0 = __float_as_uint(a.x), a1 = __float_as_uint(a.y);
    uint32_t a2 = __float_as_uint(a.z), a3 = __float_as_uint(a.w);
    uint32_t b0 = __float_as_uint(bf.x), b1 = __float_as_uint(bf.y);
    asm volatile(
        "mma.sync.aligned.m16n8k8.row.col.f32.tf32.tf32.f32 "
        "{%0,%1,%2,%3}, {%4,%5,%6,%7}, {%8,%9}, {%0,%1,%2,%3};"
        : "+f"(c.x), "+f"(c.y), "+f"(c.z), "+f"(c.w)
        : "r"(a0), "r"(a1), "r"(a2), "r"(a3), "r"(b0), "r"(b1));
}

// fp16 m16n8k16 mma, f32 accum
__device__ __forceinline__ void mmah(float4& c, const uint32_t* a,
                                     uint32_t b0, uint32_t b1) {
    asm volatile(
        "mma.sync.aligned.m16n8k16.row.col.f32.f16.f16.f32 "
        "{%0,%1,%2,%3}, {%4,%5,%6,%7}, {%8,%9}, {%0,%1,%2,%3};"
        : "+f"(c.x), "+f"(c.y), "+f"(c.z), "+f"(c.w)
        : "r"(a[0]), "r"(a[1]), "r"(a[2]), "r"(a[3]), "r"(b0), "r"(b1));
}

__device__ __forceinline__ void ldm4(uint32_t* f, uint32_t addr) {
    asm volatile("ldmatrix.sync.aligned.m8n8.x4.shared.b16 {%0,%1,%2,%3}, [%4];"
        : "=r"(f[0]), "=r"(f[1]), "=r"(f[2]), "=r"(f[3]) : "r"(addr));
}

__device__ __forceinline__ void cp16(uint32_t saddr, const void* g) {
    asm volatile("cp.async.ca.shared.global [%0], [%1], 16;"
        :: "r"(saddr), "l"(g) : "memory");
}
__device__ __forceinline__ void cpcommit() {
    asm volatile("cp.async.commit_group;" ::: "memory");
}
template<int N> __device__ __forceinline__ void cpwait() {
    asm volatile("cp.async.wait_group %0;" :: "n"(N) : "memory");
}

// fp16 q/k tiles: 128 rows x 64 halfs, stride 144 B
#define HSB 144
#define HTILE (128*HSB)      // 18432 B
// E tiles: 128 rows x 128 halfs, stride 272 B.  V tiles: 64 rows x 128, stride 272.
#define ESB 272
#define ETILE (128*ESB)      // 34816 B
#define VTILE (64*ESB)       // 17408 B

__device__ __forceinline__ void stage_h(uint32_t sbase, const __half* g) {
    for (int c = threadIdx.x; c < 1024; c += blockDim.x) {
        int r = c >> 3, ch = c & 7;
        cp16(sbase + r * HSB + ch * 16, g + (size_t)r * DH + ch * 8);
    }
}
// stage 128x128 fp16 E tile; global row stride TT halfs
__device__ __forceinline__ void stage_E(uint32_t sbase, const __half* g) {
    for (int c = threadIdx.x; c < 2048; c += blockDim.x) {
        int r = c >> 4, ch = c & 15;
        cp16(sbase + r * ESB + ch * 16, g + (size_t)r * TT + ch * 8);
    }
}
// stage 64x128 fp16 V tile; global row stride TT halfs
__device__ __forceinline__ void stage_V(uint32_t sbase, const __half* g) {
    for (int c = threadIdx.x; c < 1024; c += blockDim.x) {
        int r = c >> 4, ch = c & 15;
        cp16(sbase + r * ESB + ch * 16, g + (size_t)r * TT + ch * 8);
    }
}

// ===========================================================================
// proj smem layouts (tf32 fragment order — proven)
// ===========================================================================
#define F_KS (8*128 + 4)
#define G_KS8  (8*64 + 4)
#define F_SZ   (8*F_KS)
#define G_SZ8  (8*G_KS8)

#define FILL_F(Fp, LOAD4)                                                     \
    for (int c = threadIdx.x; c < 2048; c += 256) {                           \
        int row = c >> 4, q4 = c & 15;                                        \
        float4 v = LOAD4;                                                     \
        int kk = q4 >> 1, jh = q4 & 1;                                        \
        int rb = row >> 4, jl = (row >> 3) & 1, gr = row & 7;                 \
        int base = kk * F_KS + rb * 128 + gr * 16 + jh * 2 + jl;              \
        (Fp)[base +  0] = tf32r(v.x);                                         \
        (Fp)[base +  4] = tf32r(v.y);                                         \
        (Fp)[base +  8] = tf32r(v.z);                                         \
        (Fp)[base + 12] = tf32r(v.w);                                         \
    }

#define FILL_G_NMAJ(Gp, GKS, NCOLS, LOAD4)                                    \
    for (int c = threadIdx.x; c < (NCOLS)*16; c += 256) {                     \
        int n = c >> 4, q4 = c & 15;                                          \
        float4 v = LOAD4;                                                     \
        int kk = q4 >> 1, jh = q4 & 1;                                        \
        int nb = n >> 3, gc = n & 7;                                          \
        int base = kk * (GKS) + nb * 64 + gc * 8 + jh;                        \
        (Gp)[base + 0] = tf32r(v.x);                                          \
        (Gp)[base + 2] = tf32r(v.y);                                          \
        (Gp)[base + 4] = tf32r(v.z);                                          \
        (Gp)[base + 6] = tf32r(v.w);                                          \
    }

// ===========================================================================
// K1: QKV projections. q,k -> fp16; v -> fp32.
// ===========================================================================
__global__ __launch_bounds__(256) void proj_kernel(
        const float* __restrict__ x,
        const float* __restrict__ Wq,
        const float* __restrict__ Wk,
        const float* __restrict__ Wv) {
    extern __shared__ char smemc[];
    float* F = (float*)smemc;
    float* G = F + F_SZ;

    const int row0 = blockIdx.x * 128;
    const float* W = (blockIdx.y == 0) ? Wq : (blockIdx.y == 1) ? Wk : Wv;

    const int tid = threadIdx.x, lane = tid & 31, w = tid >> 5;
    const int wm = w & 3, wn = w >> 2;

    float4 acc[2][4];
#pragma unroll
    for (int i = 0; i < 2; i++)
#pragma unroll
        for (int j = 0; j < 4; j++) acc[i][j] = make_float4(0.f,0.f,0.f,0.f);

    for (int kc = 0; kc < DM; kc += 64) {
        FILL_F(F, (*(const float4*)&x[(size_t)(row0 + row) * DM + kc + q4 * 4]))
        FILL_G_NMAJ(G, G_KS8, 64, (*(const float4*)&W[(size_t)n * DM + kc + q4 * 4]))
        __syncthreads();
#pragma unroll
        for (int kk = 0; kk < 8; kk++) {
            float4 a0 = *(const float4*)&F[kk * F_KS + (wm * 2 + 0) * 128 + lane * 4];
            float4 a1 = *(const float4*)&F[kk * F_KS + (wm * 2 + 1) * 128 + lane * 4];
#pragma unroll
            for (int nt = 0; nt < 4; nt++) {
                float2 bv = *(const float2*)&G[kk * G_KS8 + (wn * 4 + nt) * 64 + lane * 2];
                mma8(acc[0][nt], a0, bv);
                mma8(acc[1][nt], a1, bv);
            }
        }
        __syncthreads();
    }

    const int gr = lane >> 2, tc = lane & 3;
#pragma unroll
    for (int mt = 0; mt < 2; mt++)
#pragma unroll
        for (int nt = 0; nt < 4; nt++) {
            int r = row0 + wm*32 + mt*16 + gr;
            int h = wn*32 + nt*8 + tc*2;
            float4 c = acc[mt][nt];
            if (blockIdx.y < 2) {
                __half* oh = (blockIdx.y == 0) ? g_qh : g_kh;
                *(__half2*)&oh[(size_t)r * DH + h]     = __floats2half2_rn(c.x, c.y);
                *(__half2*)&oh[(size_t)(r+8) * DH + h] = __floats2half2_rn(c.z, c.w);
            } else {
                *(float2*)&g_v[(size_t)r * DH + h]     = make_float2(c.x, c.y);
                *(float2*)&g_v[(size_t)(r+8) * DH + h] = make_float2(c.z, c.w);
            }
        }
}

// ===========================================================================
// zero kernels
// ===========================================================================
__global__ void zero_colsum_kernel() {
    int i = blockIdx.x * 256 + threadIdx.x;
    if (i < BT) g_colsum[i] = 0.f;
}
__global__ void zero_out_kernel(float* __restrict__ out) {
    int i = blockIdx.x * 256 + threadIdx.x;
    if (i < BT * DH) out[i] = 0.f;
}

// ===========================================================================
// K2: colsum + E materialization.  512 threads, 16 warps, warp = 16t x 64s.
// grid (32 sb, BB, 8 strips), 2 CTA/SM target (<=64 regs).
// ===========================================================================
__global__ __launch_bounds__(512, 2) void colsum_kernel() {
    const int sb = blockIdx.x, b = blockIdx.y, strip = blockIdx.z;
    const int t_i0 = sb + strip;
    if (t_i0 >= 32) return;

    extern __shared__ char smemc[];
    const uint32_t s32 = (uint32_t)__cvta_generic_to_shared(smemc);
    const uint32_t hk = s32;
    const uint32_t hq[2] = { s32 + HTILE, s32 + 2*HTILE };
    float* colbuf = (float*)(smemc + 3*HTILE);   // [128]

    const int tid = threadIdx.x, lane = tid & 31, w = tid >> 5;
    const int wm = w & 7, wn = w >> 3;           // wm: 16-row group, wn: 64-col half
    const int g4 = lane >> 2, tc = lane & 3;
    const int s0 = sb * 128;

    if (tid < 128) colbuf[tid] = 0.f;

    const uint32_t aoff = ((lane & 15) * 72 + ((lane >> 4) << 3)) * 2;
    const uint32_t boff = (((lane & 7) + (((lane >> 4) & 1) << 3)) * 72
                           + (((lane >> 3) & 1) << 3)) * 2;

    stage_h(hk, g_kh + (size_t)(b*TT + s0) * DH);
    stage_h(hq[0], g_qh + (size_t)(b*TT + t_i0*128) * DH);
    cpcommit();

    int bi = 0;
    for (int tidx = t_i0; tidx < 32; tidx += 8, bi ^= 1) {
        if (tidx + 8 < 32) {
            stage_h(hq[bi^1], g_qh + (size_t)(b*TT + (tidx+8)*128) * DH);
            cpcommit();
            cpwait<1>();
        } else cpwait<0>();
        __syncthreads();

        float4 acc[8];
#pragma unroll
        for (int j = 0; j < 8; j++) acc[j] = make_float4(0.f,0.f,0.f,0.f);

#pragma unroll
        for (int c4 = 0; c4 < 4; c4++) {
            const int kc = c4 * 16;
            uint32_t a[4];
            ldm4(a, hq[bi] + (wm*16) * HSB + kc*2 + aoff);
#pragma unroll
            for (int nt2 = 0; nt2 < 4; nt2++) {
                uint32_t bf[4];
                ldm4(bf, hk + (wn*64 + nt2*16) * HSB + kc*2 + boff);
                mmah(acc[nt2*2],   a, bf[0], bf[1]);
                mmah(acc[nt2*2+1], a, bf[2], bf[3]);
            }
        }

        const bool diag = (tidx == sb);
        const int t0 = tidx * 128;
        const int t = t0 + wm*16 + g4;
        float colp[8][2];
#pragma unroll
        for (int nt = 0; nt < 8; nt++) { colp[nt][0] = 0.f; colp[nt][1] = 0.f; }

#pragma unroll
        for (int nt = 0; nt < 8; nt++) {
            float4 c = acc[nt];
            int s = s0 + wn*64 + nt*8 + tc*2;
            float e0, e1, e2, e3;
            if (diag) {
                e0 = (s     <= t    ) ? __expf(c.x * 0.125f) : 0.f;
                e1 = (s + 1 <= t    ) ? __expf(c.y * 0.125f) : 0.f;
                e2 = (s     <= t + 8) ? __expf(c.z * 0.125f) : 0.f;
                e3 = (s + 1 <= t + 8) ? __expf(c.w * 0.125f) : 0.f;
            } else {
                e0 = __expf(c.x * 0.125f); e1 = __expf(c.y * 0.125f);
                e2 = __expf(c.z * 0.125f); e3 = __expf(c.w * 0.125f);
            }
            *(__half2*)&g_E[((size_t)(b*TT + t))*TT + s]     = __floats2half2_rn(e0, e1);
            *(__half2*)&g_E[((size_t)(b*TT + t + 8))*TT + s] = __floats2half2_rn(e2, e3);
            colp[nt][0] += e0 + e2;
            colp[nt][1] += e1 + e3;
        }

#pragma unroll
        for (int nt = 0; nt < 8; nt++)
#pragma unroll
            for (int par = 0; par < 2; par++) {
                float vsum = colp[nt][par];
                vsum += __shfl_xor_sync(0xffffffffu, vsum, 4);
                vsum += __shfl_xor_sync(0xffffffffu, vsum, 8);
                vsum += __shfl_xor_sync(0xffffffffu, vsum, 16);
                if (g4 == 0)
                    atomicAdd(&colbuf[wn*64 + nt*8 + tc*2 + par], vsum);
            }
        __syncthreads();
    }

    if (tid < 128)
        atomicAdd(&g_colsum[b*TT + s0 + tid], colbuf[tid]);
}

// ===========================================================================
// K3: g_vshT[b][h][s] = fp16(v[s,h] / colsum[s])  — tiled transpose
// grid (TT/64, BB), 256 thr
// ===========================================================================
__global__ __launch_bounds__(256) void vshT_kernel() {
    __shared__ float tile[64][65];
    const int s0 = blockIdx.x * 64, b = blockIdx.y;
    for (int idx = threadIdx.x; idx < 4096; idx += 256) {
        int s = idx >> 6, h = idx & 63;
        tile[s][h] = g_v[(size_t)(b*TT + s0 + s) * DH + h] / g_colsum[b*TT + s0 + s];
    }
    __syncthreads();
    for (int idx = threadIdx.x; idx < 2048; idx += 256) {
        int h = idx >> 5, sp = idx & 31;
        *(__half2*)&g_vshT[((size_t)(b*DH + h)) * TT + s0 + sp*2] =
            __floats2half2_rn(tile[sp*2][h], tile[sp*2+1][h]);
    }
}

// ===========================================================================
// K4: pure fp16 GEMM AV.  512 threads, 16 warps, warp = 16t x 32h.
// grid (32 tb reversed, 8 strips, BB), s-tiles of 128, double-buffered.
// ===========================================================================
__global__ __launch_bounds__(512, 2) void av_kernel(float* __restrict__ out) {
    const int tb = 31 - blockIdx.x;
    const int strip = blockIdx.y;
    const int b = blockIdx.z;
    const int t0 = tb * 128;
    if (strip > tb) return;

    extern __shared__ char smemc[];
    const uint32_t s32 = (uint32_t)__cvta_generic_to_shared(smemc);
    const uint32_t eb[2] = { s32, s32 + ETILE };
    const uint32_t vb[2] = { s32 + 2*ETILE, s32 + 2*ETILE + VTILE };

    const int tid = threadIdx.x, lane = tid & 31, w = tid >> 5;
    const int wm = w & 7, wn = w >> 3;           // wm: 16-row group, wn: 32-h half
    const int g4 = lane >> 2, tc = lane & 3;

    const uint32_t aoff = (lane & 15) * ESB + ((lane >> 4) << 4);
    const uint32_t boff = ((lane & 7) + (((lane >> 4) & 1) << 3)) * ESB
                        + (((lane >> 3) & 1) << 4);

    const __half* Ebase = g_E + ((size_t)(b*TT + t0)) * TT;
    const __half* Vbase = g_vshT + (size_t)b * DH * TT;

    stage_E(eb[0], Ebase + strip*128);
    stage_V(vb[0], Vbase + strip*128);
    cpcommit();

    float4 oacc[4];
#pragma unroll
    for (int n = 0; n < 4; n++) oacc[n] = make_float4(0.f,0.f,0.f,0.f);

    int bi = 0;
    for (int sidx = strip; sidx <= tb; sidx += 8, bi ^= 1) {
        if (sidx + 8 <= tb) {
            stage_E(eb[bi^1], Ebase + (sidx+8)*128);
            stage_V(vb[bi^1], Vbase + (sidx+8)*128);
            cpcommit();
            cpwait<1>();
        } else cpwait<0>();
        __syncthreads();

#pragma unroll
        for (int c8 = 0; c8 < 8; c8++) {
            const int kc = c8 * 16;
            uint32_t a[4];
            ldm4(a, eb[bi] + (wm*16) * ESB + kc*2 + aoff);
#pragma unroll
            for (int nt2 = 0; nt2 < 2; nt2++) {
                uint32_t bf[4];
                ldm4(bf, vb[bi] + (wn*32 + nt2*16) * ESB + kc*2 + boff);
                mmah(oacc[nt2*2],   a, bf[0], bf[1]);
                mmah(oacc[nt2*2+1], a, bf[2], bf[3]);
            }
        }
        __syncthreads();
    }

    const size_t r = (size_t)(b*TT + t0 + wm*16 + g4);
#pragma unroll
    for (int n = 0; n < 4; n++) {
        int h = wn*32 + n*8 + tc*2;
        atomicAdd(&out[r * DH + h],           oacc[n].x);
        atomicAdd(&out[r * DH + h + 1],       oacc[n].y);
        atomicAdd(&out[(r + 8) * DH + h],     oacc[n].z);
        atomicAdd(&out[(r + 8) * DH + h + 1], oacc[n].w);
    }
}

// ===========================================================================
// launch
// ===========================================================================
extern "C" void kernel_launch(void* const* d_in, const int* in_sizes, int n_in,
                              void* d_out, int out_size) {
    const float* x  = (const float*)d_in[0];
    const float* Wq = (const float*)d_in[1];
    const float* Wk = (const float*)d_in[2];
    const float* Wv = (const float*)d_in[3];
    float* out = (float*)d_out;

    const int smem_proj   = (F_SZ + G_SZ8) * 4;       // 49408
    const int smem_colsum = 3*HTILE + 512;            // 55808
    const int smem_av     = 2*ETILE + 2*VTILE;        // 104448

    cudaFuncSetAttribute(proj_kernel,   cudaFuncAttributeMaxDynamicSharedMemorySize, smem_proj);
    cudaFuncSetAttribute(colsum_kernel, cudaFuncAttributeMaxDynamicSharedMemorySize, smem_colsum);
    cudaFuncSetAttribute(av_kernel,     cudaFuncAttributeMaxDynamicSharedMemorySize, smem_av);

    proj_kernel<<<dim3(BT / 128, 3), 256, smem_proj>>>(x, Wq, Wk, Wv);
    zero_colsum_kernel<<<BT / 256, 256>>>();
    zero_out_kernel<<<(BT * DH) / 256, 256>>>(out);
    colsum_kernel<<<dim3(32, BB, 8), 512, smem_colsum>>>();
    vshT_kernel<<<dim3(TT / 64, BB), 256>>>();
    av_kernel<<<dim3(32, 8, BB), 512, smem_av>>>(out);
}

// round 10
// speedup vs baseline: 1.8422x; 1.1890x over previous
#include <cuda_runtime.h>
#include <cuda_fp16.h>
#include <cstdint>
#include <cstddef>

#define BB 4
#define TT 4096
#define DM 512
#define DH 64
#define BT (BB*TT)   // 16384

// ---------------- scratch (device globals; no allocation allowed) ----------
__device__ __half g_qh[BT*DH];
__device__ __half g_kh[BT*DH];
__device__ float  g_v[BT*DH];
__device__ __half g_vshT[(size_t)BB*DH*TT];   // transposed scaled v, fp16
__device__ float  g_cs_part[BB*32*8*128];     // per (b,sb,strip) colsum partials
__device__ __half g_E[(size_t)BB*TT*TT];      // masked exp scores, fp16

// ---------------- helpers ---------------------------------------------------
// fp16 m16n8k16 mma, f32 accum
__device__ __forceinline__ void mmah(float4& c, const uint32_t* a,
                                     uint32_t b0, uint32_t b1) {
    asm volatile(
        "mma.sync.aligned.m16n8k16.row.col.f32.f16.f16.f32 "
        "{%0,%1,%2,%3}, {%4,%5,%6,%7}, {%8,%9}, {%0,%1,%2,%3};"
        : "+f"(c.x), "+f"(c.y), "+f"(c.z), "+f"(c.w)
        : "r"(a[0]), "r"(a[1]), "r"(a[2]), "r"(a[3]), "r"(b0), "r"(b1));
}

__device__ __forceinline__ void ldm4(uint32_t* f, uint32_t addr) {
    asm volatile("ldmatrix.sync.aligned.m8n8.x4.shared.b16 {%0,%1,%2,%3}, [%4];"
        : "=r"(f[0]), "=r"(f[1]), "=r"(f[2]), "=r"(f[3]) : "r"(addr));
}

__device__ __forceinline__ void cp16(uint32_t saddr, const void* g) {
    asm volatile("cp.async.ca.shared.global [%0], [%1], 16;"
        :: "r"(saddr), "l"(g) : "memory");
}
__device__ __forceinline__ void cpcommit() {
    asm volatile("cp.async.commit_group;" ::: "memory");
}
template<int N> __device__ __forceinline__ void cpwait() {
    asm volatile("cp.async.wait_group %0;" :: "n"(N) : "memory");
}
__device__ __forceinline__ void sts64(uint32_t addr, uint32_t u0, uint32_t u1) {
    asm volatile("st.shared.v2.u32 [%0], {%1,%2};" :: "r"(addr), "r"(u0), "r"(u1));
}
__device__ __forceinline__ uint32_t packh2(float lo, float hi) {
    __half2 h = __floats2half2_rn(lo, hi);
    return *(uint32_t*)&h;
}

// fp16 tiles: rows x 64 halfs, stride 144 B
#define HSB 144
#define HTILE (128*HSB)      // 18432 B
#define WTILE (64*HSB)       // 9216 B
// E tiles: 128 rows x 128 halfs, stride 272 B.  V tiles: 64 rows x 128, stride 272.
#define ESB 272
#define ETILE (128*ESB)      // 34816 B
#define VTILE (64*ESB)       // 17408 B

__device__ __forceinline__ void stage_h(uint32_t sbase, const __half* g) {
    for (int c = threadIdx.x; c < 1024; c += blockDim.x) {
        int r = c >> 3, ch = c & 7;
        cp16(sbase + r * HSB + ch * 16, g + (size_t)r * DH + ch * 8);
    }
}
__device__ __forceinline__ void stage_E(uint32_t sbase, const __half* g) {
    for (int c = threadIdx.x; c < 2048; c += blockDim.x) {
        int r = c >> 4, ch = c & 15;
        cp16(sbase + r * ESB + ch * 16, g + (size_t)r * TT + ch * 8);
    }
}
__device__ __forceinline__ void stage_V(uint32_t sbase, const __half* g) {
    for (int c = threadIdx.x; c < 1024; c += blockDim.x) {
        int r = c >> 4, ch = c & 15;
        cp16(sbase + r * ESB + ch * 16, g + (size_t)r * TT + ch * 8);
    }
}

// ===========================================================================
// K1: QKV projections, full fp16 MMA. q,k -> fp16; v -> fp32.
// grid (128, 3), 256 thr. 8 k-chunks of 64, register-prefetch pipeline.
// warp: wm = w&3 (32 rows), wn = w>>2 (32 out-cols)
// ===========================================================================
__global__ __launch_bounds__(256) void proj_kernel(
        const float* __restrict__ x,
        const float* __restrict__ Wq,
        const float* __restrict__ Wk,
        const float* __restrict__ Wv) {
    extern __shared__ char smemc[];
    const uint32_t s32 = (uint32_t)__cvta_generic_to_shared(smemc);
    const uint32_t hx = s32;            // 128 x 64 halfs
    const uint32_t hw = s32 + HTILE;    // 64 x 64 halfs

    const int row0 = blockIdx.x * 128;
    const float* W = (blockIdx.y == 0) ? Wq : (blockIdx.y == 1) ? Wk : Wv;

    const int tid = threadIdx.x, lane = tid & 31, w = tid >> 5;
    const int wm = w & 3, wn = w >> 2;
    const int g4 = lane >> 2, tc = lane & 3;

    const uint32_t aoff = ((lane & 15) * 72 + ((lane >> 4) << 3)) * 2;
    const uint32_t boff = (((lane & 7) + (((lane >> 4) & 1) << 3)) * 72
                           + (((lane >> 3) & 1) << 3)) * 2;

    float4 px[8], pw[4];
#pragma unroll
    for (int j = 0; j < 8; j++) {
        int f = tid + 256*j, r = f >> 4, c4 = f & 15;
        px[j] = *(const float4*)&x[(size_t)(row0 + r) * DM + c4 * 4];
    }
#pragma unroll
    for (int j = 0; j < 4; j++) {
        int f = tid + 256*j, n = f >> 4, c4 = f & 15;
        pw[j] = *(const float4*)&W[(size_t)n * DM + c4 * 4];
    }

    float4 acc[2][4];
#pragma unroll
    for (int i = 0; i < 2; i++)
#pragma unroll
        for (int j = 0; j < 4; j++) acc[i][j] = make_float4(0.f,0.f,0.f,0.f);

    for (int kc = 0; kc < 8; kc++) {
#pragma unroll
        for (int j = 0; j < 8; j++) {
            int f = tid + 256*j, r = f >> 4, c4 = f & 15;
            sts64(hx + r*HSB + c4*8, packh2(px[j].x, px[j].y), packh2(px[j].z, px[j].w));
        }
#pragma unroll
        for (int j = 0; j < 4; j++) {
            int f = tid + 256*j, n = f >> 4, c4 = f & 15;
            sts64(hw + n*HSB + c4*8, packh2(pw[j].x, pw[j].y), packh2(pw[j].z, pw[j].w));
        }
        __syncthreads();

        if (kc < 7) {
            const int ko = (kc + 1) * 64;
#pragma unroll
            for (int j = 0; j < 8; j++) {
                int f = tid + 256*j, r = f >> 4, c4 = f & 15;
                px[j] = *(const float4*)&x[(size_t)(row0 + r) * DM + ko + c4 * 4];
            }
#pragma unroll
            for (int j = 0; j < 4; j++) {
                int f = tid + 256*j, n = f >> 4, c4 = f & 15;
                pw[j] = *(const float4*)&W[(size_t)n * DM + ko + c4 * 4];
            }
        }

#pragma unroll
        for (int c4i = 0; c4i < 4; c4i++) {
            const int k16 = c4i * 16;
            uint32_t a0[4], a1[4];
            ldm4(a0, hx + (wm*32)      * HSB + k16*2 + aoff);
            ldm4(a1, hx + (wm*32 + 16) * HSB + k16*2 + aoff);
#pragma unroll
            for (int nt2 = 0; nt2 < 2; nt2++) {
                uint32_t bf[4];
                ldm4(bf, hw + (wn*32 + nt2*16) * HSB + k16*2 + boff);
                mmah(acc[0][nt2*2],   a0, bf[0], bf[1]);
                mmah(acc[0][nt2*2+1], a0, bf[2], bf[3]);
                mmah(acc[1][nt2*2],   a1, bf[0], bf[1]);
                mmah(acc[1][nt2*2+1], a1, bf[2], bf[3]);
            }
        }
        __syncthreads();
    }

#pragma unroll
    for (int mt = 0; mt < 2; mt++)
#pragma unroll
        for (int nt2 = 0; nt2 < 2; nt2++)
#pragma unroll
            for (int p = 0; p < 2; p++) {
                int r = row0 + wm*32 + mt*16 + g4;
                int h = wn*32 + nt2*16 + p*8 + tc*2;
                float4 c = acc[mt][nt2*2 + p];
                if (blockIdx.y < 2) {
                    __half* oh = (blockIdx.y == 0) ? g_qh : g_kh;
                    *(__half2*)&oh[(size_t)r * DH + h]     = __floats2half2_rn(c.x, c.y);
                    *(__half2*)&oh[(size_t)(r+8) * DH + h] = __floats2half2_rn(c.z, c.w);
                } else {
                    *(float2*)&g_v[(size_t)r * DH + h]     = make_float2(c.x, c.y);
                    *(float2*)&g_v[(size_t)(r+8) * DH + h] = make_float2(c.z, c.w);
                }
            }
}

// ===========================================================================
// K2: colsum partials + E materialization.  512 threads, warp = 16t x 64s.
// grid (32 sb, BB, 8 strips). Writes g_cs_part[(b*32+sb)*8+strip][*].
// ===========================================================================
__global__ __launch_bounds__(512, 2) void colsum_kernel() {
    const int sb = blockIdx.x, b = blockIdx.y, strip = blockIdx.z;
    const int t_i0 = sb + strip;
    if (t_i0 >= 32) return;

    extern __shared__ char smemc[];
    const uint32_t s32 = (uint32_t)__cvta_generic_to_shared(smemc);
    const uint32_t hk = s32;
    const uint32_t hq[2] = { s32 + HTILE, s32 + 2*HTILE };
    float* colbuf = (float*)(smemc + 3*HTILE);   // [128]

    const int tid = threadIdx.x, lane = tid & 31, w = tid >> 5;
    const int wm = w & 7, wn = w >> 3;
    const int g4 = lane >> 2, tc = lane & 3;
    const int s0 = sb * 128;

    if (tid < 128) colbuf[tid] = 0.f;

    const uint32_t aoff = ((lane & 15) * 72 + ((lane >> 4) << 3)) * 2;
    const uint32_t boff = (((lane & 7) + (((lane >> 4) & 1) << 3)) * 72
                           + (((lane >> 3) & 1) << 3)) * 2;

    stage_h(hk, g_kh + (size_t)(b*TT + s0) * DH);
    stage_h(hq[0], g_qh + (size_t)(b*TT + t_i0*128) * DH);
    cpcommit();

    int bi = 0;
    for (int tidx = t_i0; tidx < 32; tidx += 8, bi ^= 1) {
        if (tidx + 8 < 32) {
            stage_h(hq[bi^1], g_qh + (size_t)(b*TT + (tidx+8)*128) * DH);
            cpcommit();
            cpwait<1>();
        } else cpwait<0>();
        __syncthreads();

        float4 acc[8];
#pragma unroll
        for (int j = 0; j < 8; j++) acc[j] = make_float4(0.f,0.f,0.f,0.f);

#pragma unroll
        for (int c4 = 0; c4 < 4; c4++) {
            const int kc = c4 * 16;
            uint32_t a[4];
            ldm4(a, hq[bi] + (wm*16) * HSB + kc*2 + aoff);
#pragma unroll
            for (int nt2 = 0; nt2 < 4; nt2++) {
                uint32_t bf[4];
                ldm4(bf, hk + (wn*64 + nt2*16) * HSB + kc*2 + boff);
                mmah(acc[nt2*2],   a, bf[0], bf[1]);
                mmah(acc[nt2*2+1], a, bf[2], bf[3]);
            }
        }

        const bool diag = (tidx == sb);
        const int t0 = tidx * 128;
        const int t = t0 + wm*16 + g4;
        float colp[8][2];
#pragma unroll
        for (int nt = 0; nt < 8; nt++) { colp[nt][0] = 0.f; colp[nt][1] = 0.f; }

#pragma unroll
        for (int nt = 0; nt < 8; nt++) {
            float4 c = acc[nt];
            int s = s0 + wn*64 + nt*8 + tc*2;
            float e0, e1, e2, e3;
            if (diag) {
                e0 = (s     <= t    ) ? __expf(c.x * 0.125f) : 0.f;
                e1 = (s + 1 <= t    ) ? __expf(c.y * 0.125f) : 0.f;
                e2 = (s     <= t + 8) ? __expf(c.z * 0.125f) : 0.f;
                e3 = (s + 1 <= t + 8) ? __expf(c.w * 0.125f) : 0.f;
            } else {
                e0 = __expf(c.x * 0.125f); e1 = __expf(c.y * 0.125f);
                e2 = __expf(c.z * 0.125f); e3 = __expf(c.w * 0.125f);
            }
            *(__half2*)&g_E[((size_t)(b*TT + t))*TT + s]     = __floats2half2_rn(e0, e1);
            *(__half2*)&g_E[((size_t)(b*TT + t + 8))*TT + s] = __floats2half2_rn(e2, e3);
            colp[nt][0] += e0 + e2;
            colp[nt][1] += e1 + e3;
        }

#pragma unroll
        for (int nt = 0; nt < 8; nt++)
#pragma unroll
            for (int par = 0; par < 2; par++) {
                float vsum = colp[nt][par];
                vsum += __shfl_xor_sync(0xffffffffu, vsum, 4);
                vsum += __shfl_xor_sync(0xffffffffu, vsum, 8);
                vsum += __shfl_xor_sync(0xffffffffu, vsum, 16);
                if (g4 == 0)
                    atomicAdd(&colbuf[wn*64 + nt*8 + tc*2 + par], vsum);
            }
        __syncthreads();
    }

    if (tid < 128)
        g_cs_part[((b*32 + sb)*8 + strip)*128 + tid] = colbuf[tid];
}

// ===========================================================================
// K3: zero out + reduce colsum partials + g_vshT[b][h][s] = fp16(v/cs).
// grid (TT/64, BB), 256 thr
// ===========================================================================
__global__ __launch_bounds__(256) void vshT_kernel(float* __restrict__ out) {
    __shared__ float tile[64][65];
    __shared__ float cssm[64];
    const int s0 = blockIdx.x * 64, b = blockIdx.y;

    // zero this CTA's slice of out (BT*DH / 256 CTAs = 4096 floats)
    {
        int cta = b * gridDim.x + blockIdx.x;
        float4* o4 = (float4*)(out + (size_t)cta * 4096);
        for (int i = threadIdx.x; i < 1024; i += 256)
            o4[i] = make_float4(0.f,0.f,0.f,0.f);
    }

    if (threadIdx.x < 64) {
        int sb = s0 >> 7, idx = (s0 & 127) + threadIdx.x;
        const float* part = g_cs_part + ((b*32 + sb)*8)*128 + idx;
        float cs = 0.f;
#pragma unroll
        for (int j = 0; j < 8; j++) cs += part[j*128];
        cssm[threadIdx.x] = cs;
    }
    __syncthreads();

    for (int idx = threadIdx.x; idx < 4096; idx += 256) {
        int s = idx >> 6, h = idx & 63;
        tile[s][h] = g_v[(size_t)(b*TT + s0 + s) * DH + h] / cssm[s];
    }
    __syncthreads();
    for (int idx = threadIdx.x; idx < 2048; idx += 256) {
        int h = idx >> 5, sp = idx & 31;
        *(__half2*)&g_vshT[((size_t)(b*DH + h)) * TT + s0 + sp*2] =
            __floats2half2_rn(tile[sp*2][h], tile[sp*2+1][h]);
    }
}

// ===========================================================================
// K4: pure fp16 GEMM AV.  512 threads, warp = 16t x 32h.
// grid (32 tb reversed, 8 strips, BB), s-tiles of 128, double-buffered.
// ===========================================================================
__global__ __launch_bounds__(512, 2) void av_kernel(float* __restrict__ out) {
    const int tb = 31 - blockIdx.x;
    const int strip = blockIdx.y;
    const int b = blockIdx.z;
    const int t0 = tb * 128;
    if (strip > tb) return;

    extern __shared__ char smemc[];
    const uint32_t s32 = (uint32_t)__cvta_generic_to_shared(smemc);
    const uint32_t eb[2] = { s32, s32 + ETILE };
    const uint32_t vb[2] = { s32 + 2*ETILE, s32 + 2*ETILE + VTILE };

    const int tid = threadIdx.x, lane = tid & 31, w = tid >> 5;
    const int wm = w & 7, wn = w >> 3;
    const int g4 = lane >> 2, tc = lane & 3;

    const uint32_t aoff = (lane & 15) * ESB + ((lane >> 4) << 4);
    const uint32_t boff = ((lane & 7) + (((lane >> 4) & 1) << 3)) * ESB
                        + (((lane >> 3) & 1) << 4);

    const __half* Ebase = g_E + ((size_t)(b*TT + t0)) * TT;
    const __half* Vbase = g_vshT + (size_t)b * DH * TT;

    stage_E(eb[0], Ebase + strip*128);
    stage_V(vb[0], Vbase + strip*128);
    cpcommit();

    float4 oacc[4];
#pragma unroll
    for (int n = 0; n < 4; n++) oacc[n] = make_float4(0.f,0.f,0.f,0.f);

    int bi = 0;
    for (int sidx = strip; sidx <= tb; sidx += 8, bi ^= 1) {
        if (sidx + 8 <= tb) {
            stage_E(eb[bi^1], Ebase + (sidx+8)*128);
            stage_V(vb[bi^1], Vbase + (sidx+8)*128);
            cpcommit();
            cpwait<1>();
        } else cpwait<0>();
        __syncthreads();

#pragma unroll
        for (int c8 = 0; c8 < 8; c8++) {
            const int kc = c8 * 16;
            uint32_t a[4];
            ldm4(a, eb[bi] + (wm*16) * ESB + kc*2 + aoff);
#pragma unroll
            for (int nt2 = 0; nt2 < 2; nt2++) {
                uint32_t bf[4];
                ldm4(bf, vb[bi] + (wn*32 + nt2*16) * ESB + kc*2 + boff);
                mmah(oacc[nt2*2],   a, bf[0], bf[1]);
                mmah(oacc[nt2*2+1], a, bf[2], bf[3]);
            }
        }
        __syncthreads();
    }

    const size_t r = (size_t)(b*TT + t0 + wm*16 + g4);
#pragma unroll
    for (int n = 0; n < 4; n++) {
        int h = wn*32 + n*8 + tc*2;
        atomicAdd(&out[r * DH + h],           oacc[n].x);
        atomicAdd(&out[r * DH + h + 1],       oacc[n].y);
        atomicAdd(&out[(r + 8) * DH + h],     oacc[n].z);
        atomicAdd(&out[(r + 8) * DH + h + 1], oacc[n].w);
    }
}

// ===========================================================================
// launch
// ===========================================================================
extern "C" void kernel_launch(void* const* d_in, const int* in_sizes, int n_in,
                              void* d_out, int out_size) {
    const float* x  = (const float*)d_in[0];
    const float* Wq = (const float*)d_in[1];
    const float* Wk = (const float*)d_in[2];
    const float* Wv = (const float*)d_in[3];
    float* out = (float*)d_out;

    const int smem_proj   = HTILE + WTILE;            // 27648
    const int smem_colsum = 3*HTILE + 512;            // 55808
    const int smem_av     = 2*ETILE + 2*VTILE;        // 104448

    cudaFuncSetAttribute(proj_kernel,   cudaFuncAttributeMaxDynamicSharedMemorySize, smem_proj);
    cudaFuncSetAttribute(colsum_kernel, cudaFuncAttributeMaxDynamicSharedMemorySize, smem_colsum);
    cudaFuncSetAttribute(av_kernel,     cudaFuncAttributeMaxDynamicSharedMemorySize, smem_av);

    proj_kernel<<<dim3(BT / 128, 3), 256, smem_proj>>>(x, Wq, Wk, Wv);
    colsum_kernel<<<dim3(32, BB, 8), 512, smem_colsum>>>();
    vshT_kernel<<<dim3(TT / 64, BB), 256>>>(out);
    av_kernel<<<dim3(32, 8, BB), 512, smem_av>>>(out);
}

// round 11
// speedup vs baseline: 1.9554x; 1.0614x over previous
#include <cuda_runtime.h>
#include <cuda_fp16.h>
#include <cstdint>
#include <cstddef>

#define BB 4
#define TT 4096
#define DM 512
#define DH 64
#define BT (BB*TT)   // 16384

// q pre-scale: 0.125 * log2(e)  (score GEMM then feeds ex2 directly)
#define QSCALE 0.18033688011112042f

// ---------------- scratch (device globals; no allocation allowed) ----------
__device__ __half g_qh[BT*DH];
__device__ __half g_kh[BT*DH];
__device__ float  g_v[BT*DH];
__device__ __half g_vshT[(size_t)BB*DH*TT];   // transposed scaled v, fp16
__device__ float  g_cs_part[BB*32*8*128];     // per (b,sb,strip) colsum partials
__device__ __half g_E[(size_t)BB*TT*TT];      // masked exp scores, fp16

// ---------------- helpers ---------------------------------------------------
__device__ __forceinline__ float ex2f(float x) {
    float y;
    asm("ex2.approx.ftz.f32 %0, %1;" : "=f"(y) : "f"(x));
    return y;
}

// fp16 m16n8k16 mma, f32 accum
__device__ __forceinline__ void mmah(float4& c, const uint32_t* a,
                                     uint32_t b0, uint32_t b1) {
    asm volatile(
        "mma.sync.aligned.m16n8k16.row.col.f32.f16.f16.f32 "
        "{%0,%1,%2,%3}, {%4,%5,%6,%7}, {%8,%9}, {%0,%1,%2,%3};"
        : "+f"(c.x), "+f"(c.y), "+f"(c.z), "+f"(c.w)
        : "r"(a[0]), "r"(a[1]), "r"(a[2]), "r"(a[3]), "r"(b0), "r"(b1));
}

__device__ __forceinline__ void ldm4(uint32_t* f, uint32_t addr) {
    asm volatile("ldmatrix.sync.aligned.m8n8.x4.shared.b16 {%0,%1,%2,%3}, [%4];"
        : "=r"(f[0]), "=r"(f[1]), "=r"(f[2]), "=r"(f[3]) : "r"(addr));
}

__device__ __forceinline__ void cp16(uint32_t saddr, const void* g) {
    asm volatile("cp.async.ca.shared.global [%0], [%1], 16;"
        :: "r"(saddr), "l"(g) : "memory");
}
__device__ __forceinline__ void cpcommit() {
    asm volatile("cp.async.commit_group;" ::: "memory");
}
template<int N> __device__ __forceinline__ void cpwait() {
    asm volatile("cp.async.wait_group %0;" :: "n"(N) : "memory");
}
__device__ __forceinline__ void sts64(uint32_t addr, uint32_t u0, uint32_t u1) {
    asm volatile("st.shared.v2.u32 [%0], {%1,%2};" :: "r"(addr), "r"(u0), "r"(u1));
}
__device__ __forceinline__ uint32_t packh2(float lo, float hi) {
    __half2 h = __floats2half2_rn(lo, hi);
    return *(uint32_t*)&h;
}

// fp16 tiles: rows x 64 halfs, stride 144 B
#define HSB 144
#define HTILE (128*HSB)      // 18432 B
#define WTILE (64*HSB)       // 9216 B
// E tiles: 128 rows x 128 halfs, stride 272 B.  V tiles: 64 rows x 128, stride 272.
#define ESB 272
#define ETILE (128*ESB)      // 34816 B
#define VTILE (64*ESB)       // 17408 B

__device__ __forceinline__ void stage_h(uint32_t sbase, const __half* g) {
    for (int c = threadIdx.x; c < 1024; c += blockDim.x) {
        int r = c >> 3, ch = c & 7;
        cp16(sbase + r * HSB + ch * 16, g + (size_t)r * DH + ch * 8);
    }
}
__device__ __forceinline__ void stage_E(uint32_t sbase, const __half* g) {
    for (int c = threadIdx.x; c < 2048; c += blockDim.x) {
        int r = c >> 4, ch = c & 15;
        cp16(sbase + r * ESB + ch * 16, g + (size_t)r * TT + ch * 8);
    }
}
__device__ __forceinline__ void stage_V(uint32_t sbase, const __half* g) {
    for (int c = threadIdx.x; c < 1024; c += blockDim.x) {
        int r = c >> 4, ch = c & 15;
        cp16(sbase + r * ESB + ch * 16, g + (size_t)r * TT + ch * 8);
    }
}

// ===========================================================================
// K1: QKV projections, full fp16 MMA. q (pre-scaled), k -> fp16; v -> fp32.
// ===========================================================================
__global__ __launch_bounds__(256) void proj_kernel(
        const float* __restrict__ x,
        const float* __restrict__ Wq,
        const float* __restrict__ Wk,
        const float* __restrict__ Wv) {
    extern __shared__ char smemc[];
    const uint32_t s32 = (uint32_t)__cvta_generic_to_shared(smemc);
    const uint32_t hx = s32;            // 128 x 64 halfs
    const uint32_t hw = s32 + HTILE;    // 64 x 64 halfs

    const int row0 = blockIdx.x * 128;
    const float* W = (blockIdx.y == 0) ? Wq : (blockIdx.y == 1) ? Wk : Wv;

    const int tid = threadIdx.x, lane = tid & 31, w = tid >> 5;
    const int wm = w & 3, wn = w >> 2;
    const int g4 = lane >> 2, tc = lane & 3;

    const uint32_t aoff = ((lane & 15) * 72 + ((lane >> 4) << 3)) * 2;
    const uint32_t boff = (((lane & 7) + (((lane >> 4) & 1) << 3)) * 72
                           + (((lane >> 3) & 1) << 3)) * 2;

    float4 px[8], pw[4];
#pragma unroll
    for (int j = 0; j < 8; j++) {
        int f = tid + 256*j, r = f >> 4, c4 = f & 15;
        px[j] = *(const float4*)&x[(size_t)(row0 + r) * DM + c4 * 4];
    }
#pragma unroll
    for (int j = 0; j < 4; j++) {
        int f = tid + 256*j, n = f >> 4, c4 = f & 15;
        pw[j] = *(const float4*)&W[(size_t)n * DM + c4 * 4];
    }

    float4 acc[2][4];
#pragma unroll
    for (int i = 0; i < 2; i++)
#pragma unroll
        for (int j = 0; j < 4; j++) acc[i][j] = make_float4(0.f,0.f,0.f,0.f);

    for (int kc = 0; kc < 8; kc++) {
#pragma unroll
        for (int j = 0; j < 8; j++) {
            int f = tid + 256*j, r = f >> 4, c4 = f & 15;
            sts64(hx + r*HSB + c4*8, packh2(px[j].x, px[j].y), packh2(px[j].z, px[j].w));
        }
#pragma unroll
        for (int j = 0; j < 4; j++) {
            int f = tid + 256*j, n = f >> 4, c4 = f & 15;
            sts64(hw + n*HSB + c4*8, packh2(pw[j].x, pw[j].y), packh2(pw[j].z, pw[j].w));
        }
        __syncthreads();

        if (kc < 7) {
            const int ko = (kc + 1) * 64;
#pragma unroll
            for (int j = 0; j < 8; j++) {
                int f = tid + 256*j, r = f >> 4, c4 = f & 15;
                px[j] = *(const float4*)&x[(size_t)(row0 + r) * DM + ko + c4 * 4];
            }
#pragma unroll
            for (int j = 0; j < 4; j++) {
                int f = tid + 256*j, n = f >> 4, c4 = f & 15;
                pw[j] = *(const float4*)&W[(size_t)n * DM + ko + c4 * 4];
            }
        }

#pragma unroll
        for (int c4i = 0; c4i < 4; c4i++) {
            const int k16 = c4i * 16;
            uint32_t a0[4], a1[4];
            ldm4(a0, hx + (wm*32)      * HSB + k16*2 + aoff);
            ldm4(a1, hx + (wm*32 + 16) * HSB + k16*2 + aoff);
#pragma unroll
            for (int nt2 = 0; nt2 < 2; nt2++) {
                uint32_t bf[4];
                ldm4(bf, hw + (wn*32 + nt2*16) * HSB + k16*2 + boff);
                mmah(acc[0][nt2*2],   a0, bf[0], bf[1]);
                mmah(acc[0][nt2*2+1], a0, bf[2], bf[3]);
                mmah(acc[1][nt2*2],   a1, bf[0], bf[1]);
                mmah(acc[1][nt2*2+1], a1, bf[2], bf[3]);
            }
        }
        __syncthreads();
    }

    const float sc = (blockIdx.y == 0) ? QSCALE : 1.0f;
#pragma unroll
    for (int mt = 0; mt < 2; mt++)
#pragma unroll
        for (int nt2 = 0; nt2 < 2; nt2++)
#pragma unroll
            for (int p = 0; p < 2; p++) {
                int r = row0 + wm*32 + mt*16 + g4;
                int h = wn*32 + nt2*16 + p*8 + tc*2;
                float4 c = acc[mt][nt2*2 + p];
                if (blockIdx.y < 2) {
                    __half* oh = (blockIdx.y == 0) ? g_qh : g_kh;
                    *(__half2*)&oh[(size_t)r * DH + h]     = __floats2half2_rn(c.x*sc, c.y*sc);
                    *(__half2*)&oh[(size_t)(r+8) * DH + h] = __floats2half2_rn(c.z*sc, c.w*sc);
                } else {
                    *(float2*)&g_v[(size_t)r * DH + h]     = make_float2(c.x, c.y);
                    *(float2*)&g_v[(size_t)(r+8) * DH + h] = make_float2(c.z, c.w);
                }
            }
}

// ===========================================================================
// K2: colsum partials + E materialization.  512 threads, warp = 16t x 64s.
// grid (32 sb, BB, 8 strips). Column sums accumulated in regs across the
// whole strip; single reduction at end.
// ===========================================================================
__global__ __launch_bounds__(512, 2) void colsum_kernel() {
    const int sb = blockIdx.x, b = blockIdx.y, strip = blockIdx.z;
    const int t_i0 = sb + strip;
    if (t_i0 >= 32) return;

    extern __shared__ char smemc[];
    const uint32_t s32 = (uint32_t)__cvta_generic_to_shared(smemc);
    const uint32_t hk = s32;
    const uint32_t hq[2] = { s32 + HTILE, s32 + 2*HTILE };
    float* colbuf = (float*)(smemc + 3*HTILE);   // [128]

    const int tid = threadIdx.x, lane = tid & 31, w = tid >> 5;
    const int wm = w & 7, wn = w >> 3;
    const int g4 = lane >> 2, tc = lane & 3;
    const int s0 = sb * 128;

    if (tid < 128) colbuf[tid] = 0.f;

    const uint32_t aoff = ((lane & 15) * 72 + ((lane >> 4) << 3)) * 2;
    const uint32_t boff = (((lane & 7) + (((lane >> 4) & 1) << 3)) * 72
                           + (((lane >> 3) & 1) << 3)) * 2;

    stage_h(hk, g_kh + (size_t)(b*TT + s0) * DH);
    stage_h(hq[0], g_qh + (size_t)(b*TT + t_i0*128) * DH);
    cpcommit();

    // per-strip column partial sums, held in registers across all tiles
    float colp[8][2];
#pragma unroll
    for (int nt = 0; nt < 8; nt++) { colp[nt][0] = 0.f; colp[nt][1] = 0.f; }

    int bi = 0;
    for (int tidx = t_i0; tidx < 32; tidx += 8, bi ^= 1) {
        if (tidx + 8 < 32) {
            stage_h(hq[bi^1], g_qh + (size_t)(b*TT + (tidx+8)*128) * DH);
            cpcommit();
            cpwait<1>();
        } else cpwait<0>();
        __syncthreads();

        float4 acc[8];
#pragma unroll
        for (int j = 0; j < 8; j++) acc[j] = make_float4(0.f,0.f,0.f,0.f);

#pragma unroll
        for (int c4 = 0; c4 < 4; c4++) {
            const int kc = c4 * 16;
            uint32_t a[4];
            ldm4(a, hq[bi] + (wm*16) * HSB + kc*2 + aoff);
#pragma unroll
            for (int nt2 = 0; nt2 < 4; nt2++) {
                uint32_t bf[4];
                ldm4(bf, hk + (wn*64 + nt2*16) * HSB + kc*2 + boff);
                mmah(acc[nt2*2],   a, bf[0], bf[1]);
                mmah(acc[nt2*2+1], a, bf[2], bf[3]);
            }
        }

        const bool diag = (tidx == sb);
        const int t = tidx * 128 + wm*16 + g4;

#pragma unroll
        for (int nt = 0; nt < 8; nt++) {
            float4 c = acc[nt];
            // q pre-scaled by 0.125*log2(e): exp(score/8) == 2^c
            float e0 = ex2f(c.x), e1 = ex2f(c.y);
            float e2 = ex2f(c.z), e3 = ex2f(c.w);
            if (diag) {
                int s = s0 + wn*64 + nt*8 + tc*2;
                e0 = (s     <= t    ) ? e0 : 0.f;
                e1 = (s + 1 <= t    ) ? e1 : 0.f;
                e2 = (s     <= t + 8) ? e2 : 0.f;
                e3 = (s + 1 <= t + 8) ? e3 : 0.f;
            }
            int s = s0 + wn*64 + nt*8 + tc*2;
            *(__half2*)&g_E[((size_t)(b*TT + t))*TT + s]     = __floats2half2_rn(e0, e1);
            *(__half2*)&g_E[((size_t)(b*TT + t + 8))*TT + s] = __floats2half2_rn(e2, e3);
            colp[nt][0] += e0 + e2;
            colp[nt][1] += e1 + e3;
        }
        __syncthreads();
    }

    // one reduction for the whole strip
#pragma unroll
    for (int nt = 0; nt < 8; nt++)
#pragma unroll
        for (int par = 0; par < 2; par++) {
            float vsum = colp[nt][par];
            vsum += __shfl_xor_sync(0xffffffffu, vsum, 4);
            vsum += __shfl_xor_sync(0xffffffffu, vsum, 8);
            vsum += __shfl_xor_sync(0xffffffffu, vsum, 16);
            if (g4 == 0)
                atomicAdd(&colbuf[wn*64 + nt*8 + tc*2 + par], vsum);
        }
    __syncthreads();

    if (tid < 128)
        g_cs_part[((b*32 + sb)*8 + strip)*128 + tid] = colbuf[tid];
}

// ===========================================================================
// K3: zero out + reduce colsum partials + g_vshT[b][h][s] = fp16(v/cs).
// grid (TT/64, BB), 256 thr
// ===========================================================================
__global__ __launch_bounds__(256) void vshT_kernel(float* __restrict__ out) {
    __shared__ float tile[64][65];
    __shared__ float cssm[64];
    const int s0 = blockIdx.x * 64, b = blockIdx.y;

    // zero this CTA's slice of out
    {
        int cta = b * gridDim.x + blockIdx.x;
        float4* o4 = (float4*)(out + (size_t)cta * 4096);
        for (int i = threadIdx.x; i < 1024; i += 256)
            o4[i] = make_float4(0.f,0.f,0.f,0.f);
    }

    if (threadIdx.x < 64) {
        int sb = s0 >> 7, idx = (s0 & 127) + threadIdx.x;
        const float* part = g_cs_part + ((b*32 + sb)*8)*128 + idx;
        float cs = 0.f;
#pragma unroll
        for (int j = 0; j < 8; j++) cs += part[j*128];
        cssm[threadIdx.x] = cs;
    }
    __syncthreads();

    for (int idx = threadIdx.x; idx < 4096; idx += 256) {
        int s = idx >> 6, h = idx & 63;
        tile[s][h] = g_v[(size_t)(b*TT + s0 + s) * DH + h] / cssm[s];
    }
    __syncthreads();
    for (int idx = threadIdx.x; idx < 2048; idx += 256) {
        int h = idx >> 5, sp = idx & 31;
        *(__half2*)&g_vshT[((size_t)(b*DH + h)) * TT + s0 + sp*2] =
            __floats2half2_rn(tile[sp*2][h], tile[sp*2+1][h]);
    }
}

// ===========================================================================
// K4: pure fp16 GEMM AV.  512 threads, warp = 16t x 32h.
// grid (32 tb reversed, 8 strips, BB), s-tiles of 128, double-buffered.
// ===========================================================================
__global__ __launch_bounds__(512, 2) void av_kernel(float* __restrict__ out) {
    const int tb = 31 - blockIdx.x;
    const int strip = blockIdx.y;
    const int b = blockIdx.z;
    const int t0 = tb * 128;
    if (strip > tb) return;

    extern __shared__ char smemc[];
    const uint32_t s32 = (uint32_t)__cvta_generic_to_shared(smemc);
    const uint32_t eb[2] = { s32, s32 + ETILE };
    const uint32_t vb[2] = { s32 + 2*ETILE, s32 + 2*ETILE + VTILE };

    const int tid = threadIdx.x, lane = tid & 31, w = tid >> 5;
    const int wm = w & 7, wn = w >> 3;
    const int g4 = lane >> 2, tc = lane & 3;

    const uint32_t aoff = (lane & 15) * ESB + ((lane >> 4) << 4);
    const uint32_t boff = ((lane & 7) + (((lane >> 4) & 1) << 3)) * ESB
                        + (((lane >> 3) & 1) << 4);

    const __half* Ebase = g_E + ((size_t)(b*TT + t0)) * TT;
    const __half* Vbase = g_vshT + (size_t)b * DH * TT;

    stage_E(eb[0], Ebase + strip*128);
    stage_V(vb[0], Vbase + strip*128);
    cpcommit();

    float4 oacc[4];
#pragma unroll
    for (int n = 0; n < 4; n++) oacc[n] = make_float4(0.f,0.f,0.f,0.f);

    int bi = 0;
    for (int sidx = strip; sidx <= tb; sidx += 8, bi ^= 1) {
        if (sidx + 8 <= tb) {
            stage_E(eb[bi^1], Ebase + (sidx+8)*128);
            stage_V(vb[bi^1], Vbase + (sidx+8)*128);
            cpcommit();
            cpwait<1>();
        } else cpwait<0>();
        __syncthreads();

#pragma unroll
        for (int c8 = 0; c8 < 8; c8++) {
            const int kc = c8 * 16;
            uint32_t a[4];
            ldm4(a, eb[bi] + (wm*16) * ESB + kc*2 + aoff);
#pragma unroll
            for (int nt2 = 0; nt2 < 2; nt2++) {
                uint32_t bf[4];
                ldm4(bf, vb[bi] + (wn*32 + nt2*16) * ESB + kc*2 + boff);
                mmah(oacc[nt2*2],   a, bf[0], bf[1]);
                mmah(oacc[nt2*2+1], a, bf[2], bf[3]);
            }
        }
        __syncthreads();
    }

    const size_t r = (size_t)(b*TT + t0 + wm*16 + g4);
#pragma unroll
    for (int n = 0; n < 4; n++) {
        int h = wn*32 + n*8 + tc*2;
        atomicAdd(&out[r * DH + h],           oacc[n].x);
        atomicAdd(&out[r * DH + h + 1],       oacc[n].y);
        atomicAdd(&out[(r + 8) * DH + h],     oacc[n].z);
        atomicAdd(&out[(r + 8) * DH + h + 1], oacc[n].w);
    }
}

// ===========================================================================
// launch
// ===========================================================================
extern "C" void kernel_launch(void* const* d_in, const int* in_sizes, int n_in,
                              void* d_out, int out_size) {
    const float* x  = (const float*)d_in[0];
    const float* Wq = (const float*)d_in[1];
    const float* Wk = (const float*)d_in[2];
    const float* Wv = (const float*)d_in[3];
    float* out = (float*)d_out;

    const int smem_proj   = HTILE + WTILE;            // 27648
    const int smem_colsum = 3*HTILE + 512;            // 55808
    const int smem_av     = 2*ETILE + 2*VTILE;        // 104448

    cudaFuncSetAttribute(proj_kernel,   cudaFuncAttributeMaxDynamicSharedMemorySize, smem_proj);
    cudaFuncSetAttribute(colsum_kernel, cudaFuncAttributeMaxDynamicSharedMemorySize, smem_colsum);
    cudaFuncSetAttribute(av_kernel,     cudaFuncAttributeMaxDynamicSharedMemorySize, smem_av);

    proj_kernel<<<dim3(BT / 128, 3), 256, smem_proj>>>(x, Wq, Wk, Wv);
    colsum_kernel<<<dim3(32, BB, 8), 512, smem_colsum>>>();
    vshT_kernel<<<dim3(TT / 64, BB), 256>>>(out);
    av_kernel<<<dim3(32, 8, BB), 512, smem_av>>>(out);
}